// round 14
// baseline (speedup 1.0000x reference)
#include <cuda_runtime.h>
#include <cuda_bf16.h>

#define NB  4096
#define ND  64
#define NDM 256
#define NK  32
#define NKA 16
#define NC  160   // M4 row stride; active cols per y: 98,129,129,50

#define NBLK_P   138
#define NBLK_P2S 28
#define NBLK_GF  256
#define NBLK_TOT (NBLK_P + NBLK_P2S + NBLK_GF)   // 422

// ----- device scratch -----
__device__ __align__(16) float g_M5[5*ND*NDM];   // Zq, Lk, Lv, Ck, Cv
__device__ __align__(16) float g_B6[5*NDM];      // bq, bLk, bLv, bCk, bCv
__device__ __align__(16) float g_KC[NK*NDM], g_VC[NK*NDM];
__device__ __align__(16) float g_AKC[NKA*NDM], g_AVC[NKA*NDM];
__device__ float g_an2[NK], g_aan2[NKA];
__device__ __align__(16) float g_M2T2[ND*NDM];   // (Wo@form_W)^T : [d][j]
__device__ __align__(16) float g_G[ND*ND];       // form_W^T form_W
__device__ float g_inv_sigma;
__device__ __align__(16) float g_M4[4*ND*NC];    // folded GEMM matrices
__device__ __align__(16) float g_bz[4*NC];

// flag barriers (zero-initialized at module load; reset by last block each launch)
__device__ volatile int g_f1;
__device__ volatile int g_f2;
__device__ int g_f3;

__device__ __forceinline__ float wsum(float v){
  #pragma unroll
  for(int o=16;o>0;o>>=1) v += __shfl_xor_sync(0xffffffffu,v,o);
  return v;
}
__device__ __forceinline__ float wmax(float v){
  #pragma unroll
  for(int o=16;o>0;o>>=1) v = fmaxf(v,__shfl_xor_sync(0xffffffffu,v,o));
  return v;
}
__device__ __forceinline__ float dot256(const float* __restrict__ A,
                                        const float* __restrict__ B, int lane){
  float4 a0 = *(const float4*)(A + lane*8);
  float4 a1 = *(const float4*)(A + lane*8 + 4);
  float4 b0 = *(const float4*)(B + lane*8);
  float4 b1 = *(const float4*)(B + lane*8 + 4);
  float s = a0.x*b0.x + a0.y*b0.y + a0.z*b0.z + a0.w*b0.w
          + a1.x*b1.x + a1.y*b1.y + a1.z*b1.z + a1.w*b1.w;
  return wsum(s);
}
__device__ __forceinline__ void spin_wait(volatile int* f, int target){
  if (threadIdx.x == 0){ while (*f < target) __nanosleep(128); }
  __syncthreads();
}
__device__ __forceinline__ void signal(volatile int* f){
  __syncthreads();
  __threadfence();
  if (threadIdx.x == 0) atomicAdd((int*)f, 1);
}

#define SG_STRIDE 416   // gf col offsets: y0=0 (98), y1=98 (129), y2=227 (129), y3=356 (50)

// ================= fused kernel: p | p2s | gf =================
__global__ __launch_bounds__(512, 2) void fused_kernel(
  const float* __restrict__ z,    const float* __restrict__ rw,
  const float* __restrict__ az,   const float* __restrict__ arw,
  const float* __restrict__ acz,  const float* __restrict__ ctrl,
  const float* __restrict__ ecov, const float* __restrict__ cemb,
  const float* __restrict__ canch,const float* __restrict__ acemb,
  const float* __restrict__ acanch,
  const float* __restrict__ zW,   const float* __restrict__ zb,
  const float* __restrict__ latW, const float* __restrict__ latb,
  const float* __restrict__ codeW,const float* __restrict__ codeb,
  const float* __restrict__ Wq,   const float* __restrict__ Wk,
  const float* __restrict__ Wv,   const float* __restrict__ Wo,
  const float* __restrict__ formW,const float* __restrict__ formb,
  float* __restrict__ out)
{
  __shared__ __align__(16) float su[12032];      // 47.0 KB union
  const int bid = blockIdx.x;
  const int t = threadIdx.x;
  const int w = t>>5, lane = t&31;

  if (bid < NBLK_P){
    // ================= P path (verbatim R13 logic) =================
    int blk = bid;
    float* As = su;            // [h][r*65+kk], 2x2080
    float* Bs = su + 4160;     // [h][kk*36+c], 2x2304
    if (blk < 132){
      int g, m0, n0;
      if (blk < 80){ g = blk>>4; int s = blk&15; m0=(s>>3)*32; n0=(s&7)*32; }
      else if (blk < 112){ g = 5 + ((blk-80)>>4); int s=(blk-80)&15; m0=(s>>3)*32; n0=(s&7)*32; }
      else if (blk < 128){ int s=blk-112; g=7; m0=(s>>1)*32; n0=(s&1)*32; }
      else { int s=blk-128; g=8; m0=(s>>1)*32; n0=(s&1)*32; }

      const float* Bm = (g==0)? Wq : (g==1||g==2||g==5)? Wk : (g>=7)? formW : Wv;
      const int ldb = (g>=7)? 64 : 256;

      const int h = w>>3, wi = w&7;
      const int r2 = t>>4, kg = (t&15)*4;
      const int kkB = t>>3, c4 = (t&7)*4;

      const float* Ap = cemb; bool avalid = true;
      if (g != 8){
        int grow = m0 + r2;
        if (g==0) Ap = zW + grow*256;
        else if (g==1||g==3) Ap = latW + grow*256;
        else if (g==2||g==4) Ap = codeW + grow*256;
        else if (g==7) Ap = Wo + grow*256;
        else {
          if (grow < 32) Ap = cemb + grow*256;
          else if (grow < 48) Ap = acemb + (grow-32)*256;
          else avalid = false;
        }
      }

      float4 apf[2], bpf[2]; float apf_s[2][4];

      auto loadAB = [&](int s){
        #pragma unroll
        for (int hh=0; hh<2; hh++){
          int base = hh*128 + s*64;
          if (g==8){
            #pragma unroll
            for (int p=0;p<4;p++){
              int idx = t + p*512; int kk = idx>>5, r = idx&31;
              apf_s[hh][p] = formW[(base+kk)*64 + m0 + r];
            }
          } else {
            apf[hh] = avalid ? *(const float4*)(Ap + base + kg) : make_float4(0,0,0,0);
          }
          bpf[hh] = *(const float4*)(Bm + (size_t)(base+kkB)*ldb + n0 + c4);
        }
      };
      auto storeAB = [&](){
        #pragma unroll
        for (int hh=0; hh<2; hh++){
          if (g==8){
            #pragma unroll
            for (int p=0;p<4;p++){
              int idx = t + p*512; int kk = idx>>5, r = idx&31;
              As[hh*2080 + r*65+kk] = apf_s[hh][p];
            }
          } else {
            float* a = As + hh*2080 + r2*65 + kg;
            a[0]=apf[hh].x; a[1]=apf[hh].y; a[2]=apf[hh].z; a[3]=apf[hh].w;
          }
          *(float4*)(Bs + hh*2304 + kkB*36 + c4) = bpf[hh];
        }
      };

      float4 acc = make_float4(0.f,0.f,0.f,0.f);
      auto compute = [&](){
        const float* Ah = As + h*2080;
        const float* Bh = Bs + h*2304;
        #pragma unroll 8
        for (int kk=0;kk<64;kk++){
          float av = Ah[lane*65+kk];
          float4 bv = *(const float4*)(Bh + kk*36 + wi*4);
          acc.x += av*bv.x; acc.y += av*bv.y; acc.z += av*bv.z; acc.w += av*bv.w;
        }
      };

      loadAB(0); storeAB(); __syncthreads();
      loadAB(1);
      compute(); __syncthreads();
      storeAB(); __syncthreads();
      compute();

      __syncthreads();
      float* red = su;           // 2048 floats [h][c][r]
      red[h*1024 + (wi*4+0)*32 + lane] = acc.x;
      red[h*1024 + (wi*4+1)*32 + lane] = acc.y;
      red[h*1024 + (wi*4+2)*32 + lane] = acc.z;
      red[h*1024 + (wi*4+3)*32 + lane] = acc.w;
      __syncthreads();
      #pragma unroll
      for (int ee=0; ee<2; ee++){
        int e = t + ee*512;
        float val = red[e] + red[1024+e];
        int c = e>>5, r = e&31;
        int grow = m0 + r, gcol = n0 + c;
        if (g<=4){
          const int off[5] = {0,1,3,2,4};   // Zq,Lk,Ck,Lv,Cv slot order
          g_M5[off[g]*(ND*NDM) + grow*NDM + gcol] = val;
        } else if (g<=6){
          if (grow < 48){
            float* C = (grow<32) ? ((g==5)? g_KC : g_VC) + grow*NDM + gcol
                                 : ((g==5)? g_AKC : g_AVC) + (grow-32)*NDM + gcol;
            *C = val;
          }
        } else if (g==7){
          g_M2T2[gcol*NDM + grow] = val;
        } else {
          g_G[grow*ND + gcol] = val;
        }
      }
    } else if (blk < 137){        // folded bias vectors, split-K halves
      int bb = blk - 132;
      const float* vv = (bb==0)? zb : (bb<3 ? latb : codeb);
      const float* Bm = (bb==0)? Wq : ((bb==1||bb==3)? Wk : Wv);
      float* sh = su;
      int c = t & 255, hh = t >> 8;
      float s = 0.f;
      #pragma unroll 16
      for (int i=hh*128; i<hh*128+128; i++) s += vv[i]*Bm[i*NDM+c];
      sh[t] = s;
      __syncthreads();
      if (t < 256) g_B6[bb*NDM + t] = sh[t] + sh[256+t];
    } else {                      // anchor norms
      if (t < 32) {
        float s=0.f;
        for (int i=0;i<ND;i++){ float v=canch[t*ND+i]; s+=v*v; }
        g_an2[t]=s;
      } else if (t < 48) {
        int k=t-32; float s=0.f;
        for (int i=0;i<ND;i++){ float v=acanch[k*ND+i]; s+=v*v; }
        g_aan2[k]=s;
      }
    }
    signal(&g_f1);
  }
  else if (bid < NBLK_P + NBLK_P2S){
    // ================= P2S path (waits for all p blocks) =================
    spin_wait(&g_f1, NBLK_P);
    __threadfence();
    int blk = bid - NBLK_P;
    float* sm = su;
    const float* Zq = g_M5;
    const float* Lk = g_M5 + 1*ND*NDM;
    const float* Lv = g_M5 + 2*ND*NDM;
    const float* Ck = g_M5 + 3*ND*NDM;
    const float* Cv = g_M5 + 4*ND*NDM;

    if (blk == 0){
      // sigma: 3 squarings (G^8) + 10 power iters + Rayleigh
      float* sA = sm; float* sB = sm + 4096; float* sv = sm + 8192;
      #pragma unroll
      for (int r=0;r<8;r++) sA[t + r*512] = g_G[t + r*512];
      __syncthreads();
      const int pr = (t>>4)*2, pc = (t&15)*4;
      for (int sq=0; sq<3; sq++){
        float4 ac0=make_float4(0,0,0,0), ac1=ac0;
        #pragma unroll 4
        for (int q=0;q<64;q++){
          float4 bv = *(const float4*)(sA + q*64 + pc);
          float a0=sA[pr*64+q], a1=sA[(pr+1)*64+q];
          ac0.x+=a0*bv.x; ac0.y+=a0*bv.y; ac0.z+=a0*bv.z; ac0.w+=a0*bv.w;
          ac1.x+=a1*bv.x; ac1.y+=a1*bv.y; ac1.z+=a1*bv.z; ac1.w+=a1*bv.w;
        }
        *(float4*)(sB + (pr+0)*64 + pc) = ac0;
        *(float4*)(sB + (pr+1)*64 + pc) = ac1;
        __syncthreads();
        #pragma unroll
        for (int k=0;k<2;k++) ((float4*)sA)[t*2+k] = ((const float4*)sB)[t*2+k];
        __syncthreads();
      }
      if (t < 32){
        sv[lane]=1.f; sv[lane+32]=1.f; __syncwarp();
        for (int it=0; it<10; it++){
          float y0=0.f, y1=0.f;
          for (int q=0;q<64;q++){ float vq=sv[q]; y0+=sA[q*64+lane]*vq; y1+=sA[q*64+32+lane]*vq; }
          float rn = rsqrtf(wsum(y0*y0+y1*y1));
          sv[lane]=y0*rn; sv[lane+32]=y1*rn; __syncwarp();
        }
        float p0=0.f, p1=0.f;     // Rayleigh on ORIGINAL G
        for (int q=0;q<64;q++){ float vq=sv[q]; p0+=g_G[lane*64+q]*vq; p1+=g_G[(lane+32)*64+q]*vq; }
        float lam = wsum(p0*sv[lane]+p1*sv[lane+32]);
        if (!lane) g_inv_sigma = 1.f/fmaxf(sqrtf(fmaxf(lam,0.f)),1e-8f);
      }
    } else if (blk == 1){         // anchor columns of y0 (cols 48-95)
      for (int idx=t; idx<3072; idx+=512){
        int i = idx/48, c = idx - i*48;
        g_M4[i*NC + 48 + c] = (c<16)? acanch[c*ND+i] : canch[(c-16)*ND+i];
      }
    } else if (blk == 2){         // g_bz row + u1/u2 columns
      for (int idx=t; idx<4*NC; idx+=512) g_bz[idx] = 0.f;
      __syncthreads();
      for (int j=w; j<178; j+=16){
        if (j < 48){
          const float* B = (j<16)? g_AKC+j*NDM : g_KC+(j-16)*NDM;
          float s = dot256(g_B6, B, lane);
          if (!lane) g_bz[j] = s;
        } else if (j < 50){
          const float* B = (j==48)? g_B6+NDM : g_B6+3*NDM;
          float s = dot256(g_B6, B, lane);
          if (!lane) g_bz[(j==48)?96:97] = s;
        } else if (j < 114){
          int i = j-50;
          float s = dot256(Zq+i*NDM, g_B6+NDM, lane);
          if (!lane) g_M4[i*NC+96] = s;
        } else {
          int i = j-114;
          float s = dot256(Zq+i*NDM, g_B6+3*NDM, lane);
          if (!lane) g_M4[i*NC+97] = s;
        }
      }
    } else if (blk == 3){         // w1,w2 (col 128) and vb3,vb4 (cols 48/49 of y3)
      for (int j=w; j<256; j+=16){
        float s; int r, col;
        if (j < 64)      { s = dot256(Lk+j*NDM,          g_B6,       lane); r=64+j;        col=128; }
        else if (j<128)  { s = dot256(Ck+(j-64)*NDM,     g_B6,       lane); r=128+(j-64);  col=128; }
        else if (j<192)  { s = dot256(g_M2T2+(j-128)*NDM,g_B6+2*NDM, lane); r=192+(j-128); col=48;  }
        else             { s = dot256(g_M2T2+(j-192)*NDM,g_B6+4*NDM, lane); r=192+(j-192); col=49;  }
        if (!lane) g_M4[r*NC+col] = s;
      }
    } else {
      // tile blocks 4..27: split-K 32x32 stage-2 GEMM tiles
      int tid2 = blk - 4;
      int typ = tid2>>2, sub = tid2&3, m0 = (sub>>1)*32, n0 = (sub&1)*32;
      const float* Ab; int orow, ocol, maxc, bsel;
      switch(typ){
        case 0: Ab=Zq;     orow=0;   ocol=0;  maxc=48; bsel=0; break;
        case 1: Ab=Lk;     orow=64;  ocol=0;  maxc=64; bsel=1; break;
        case 2: Ab=Lv;     orow=64;  ocol=64; maxc=64; bsel=2; break;
        case 3: Ab=Ck;     orow=128; ocol=0;  maxc=64; bsel=1; break;
        case 4: Ab=Cv;     orow=128; ocol=64; maxc=64; bsel=2; break;
        default:Ab=g_M2T2; orow=192; ocol=0;  maxc=48; bsel=3; break;
      }
      float* As0 = sm;            // [h][r*65+kk], 2x2080
      float* Bs0 = sm + 4160;     // [h][kk*36+swz], 2x2304
      const int h = w>>3, wi = w&7;
      const int r2 = t>>4, kg = (t&15)*4;
      const int cB = t>>4, kg2 = (t&15)*4;
      const float* Ap = Ab + (m0+r2)*NDM;
      int cglob = n0 + cB;
      const float* Bp;
      if (bsel==0)      Bp = (cglob<16)? g_AKC + cglob*NDM : (cglob<48)? g_KC + (cglob-16)*NDM : g_AKC;
      else if (bsel==1) Bp = g_M5 + cglob*NDM;
      else if (bsel==2) Bp = g_M2T2 + cglob*NDM;
      else              Bp = (cglob<16)? g_AVC + cglob*NDM : (cglob<48)? g_VC + (cglob-16)*NDM : g_AVC;

      float4 apf[2], bpf[2];
      auto loadAB = [&](int s){
        #pragma unroll
        for (int hh=0; hh<2; hh++){
          int base = hh*128 + s*64;
          apf[hh] = *(const float4*)(Ap + base + kg);
          bpf[hh] = *(const float4*)(Bp + base + kg2);
        }
      };
      auto storeAB = [&](){
        #pragma unroll
        for (int hh=0; hh<2; hh++){
          float* a = As0 + hh*2080 + r2*65 + kg;
          a[0]=apf[hh].x; a[1]=apf[hh].y; a[2]=apf[hh].z; a[3]=apf[hh].w;
          const float* bv = (const float*)&bpf[hh];
          #pragma unroll
          for (int i=0;i<4;i++){
            int kk = kg2+i;
            Bs0[hh*2304 + kk*36 + (cB ^ (kk&28))] = bv[i];
          }
        }
      };

      float4 acc = make_float4(0.f,0.f,0.f,0.f);
      auto compute = [&](){
        const float* Ah = As0 + h*2080;
        const float* Bh = Bs0 + h*2304;
        #pragma unroll 8
        for (int kk=0;kk<64;kk++){
          float av = Ah[lane*65+kk];
          float4 bv = *(const float4*)(Bh + kk*36 + ((wi*4) ^ (kk&28)));
          acc.x += av*bv.x; acc.y += av*bv.y; acc.z += av*bv.z; acc.w += av*bv.w;
        }
      };

      loadAB(0); storeAB(); __syncthreads();
      loadAB(1);
      compute(); __syncthreads();
      storeAB(); __syncthreads();
      compute();

      __syncthreads();
      float* red = sm;             // 2048 floats [h][c][r]
      red[h*1024 + (wi*4+0)*32 + lane] = acc.x;
      red[h*1024 + (wi*4+1)*32 + lane] = acc.y;
      red[h*1024 + (wi*4+2)*32 + lane] = acc.z;
      red[h*1024 + (wi*4+3)*32 + lane] = acc.w;
      __syncthreads();
      #pragma unroll
      for (int ee=0; ee<2; ee++){
        int e = t + ee*512;
        float val = red[e] + red[1024+e];
        int c = e>>5, r = e&31;
        int j0 = n0 + c;
        if (j0 < maxc) g_M4[(orow+m0+r)*NC + ocol + j0] = val;
      }
    }
    signal(&g_f2);
  }
  else {
    // ================= GF path =================
    float* xsT = su;              // [y][i][bb], stride 20 (5120 floats)
    float* sg  = su + 5120;       // [bat][col] (6656 floats)
    const int blk = bid - (NBLK_P + NBLK_P2S);
    const int b0 = blk*16;
    const int b = b0 + w;

    // ---- preamble (independent of p2s): xsT tiles + ceff ----
    for (int idx=t; idx<3072; idx+=512){
      int y = idx>>10, r = idx&1023, bb = r>>6, i = r&63;
      const float* X = (y==0)? z : (y==1)? az : acz;
      xsT[(y*64+i)*20 + bb] = X[(b0+bb)*ND + i];
    }
    float e0=ecov[b*ND+lane], e1=ecov[b*ND+32+lane];
    float c0g=ctrl[b*ND+lane], c1g=ctrl[b*ND+32+lane];
    float ee = wsum(e0*e0+e1*e1);
    float ec = wsum(e0*c0g+e1*c1g);
    float kk = (ee > 1e-8f) ? ec/fmaxf(ee,1e-8f) : 0.f;
    float ce0 = c0g - kk*e0, ce1 = c1g - kk*e1;
    float fb = wsum(formb[lane]*ce0 + formb[lane+32]*ce1);
    xsT[(3*64+lane)*20 + w]    = ce0;
    xsT[(3*64+32+lane)*20 + w] = ce1;

    // ---- wait for stage-2 matrices ----
    spin_wait(&g_f2, NBLK_P2S);   // includes __syncthreads (orders xsT writes too)
    __threadfence();

    // ---- GEMM phase: thread -> (y, col) ----
    if (t < 406){
      int y, col;
      if (t<98){y=0;col=t;} else if (t<227){y=1;col=t-98;}
      else if (t<356){y=2;col=t-227;} else {y=3;col=t-356;}
      const float* M  = g_M4 + (y*ND)*NC + col;
      const float* xb = xsT + (y*64)*20;
      float a0=0,a1=0,a2=0,a3=0,a4=0,a5=0,a6=0,a7=0,a8=0,a9=0,aa=0,ab=0,ac=0,ad=0,ae=0,af=0;
      #pragma unroll 4
      for (int i=0;i<64;i++){
        float mv = M[(size_t)i*NC];
        const float4* x4 = (const float4*)(xb + i*20);
        float4 v0=x4[0], v1=x4[1], v2=x4[2], v3=x4[3];
        a0+=mv*v0.x; a1+=mv*v0.y; a2+=mv*v0.z; a3+=mv*v0.w;
        a4+=mv*v1.x; a5+=mv*v1.y; a6+=mv*v1.z; a7+=mv*v1.w;
        a8+=mv*v2.x; a9+=mv*v2.y; aa+=mv*v2.z; ab+=mv*v2.w;
        ac+=mv*v3.x; ad+=mv*v3.y; ae+=mv*v3.z; af+=mv*v3.w;
      }
      float bz = g_bz[y*NC+col];
      sg[ 0*SG_STRIDE+t]=a0+bz; sg[ 1*SG_STRIDE+t]=a1+bz;
      sg[ 2*SG_STRIDE+t]=a2+bz; sg[ 3*SG_STRIDE+t]=a3+bz;
      sg[ 4*SG_STRIDE+t]=a4+bz; sg[ 5*SG_STRIDE+t]=a5+bz;
      sg[ 6*SG_STRIDE+t]=a6+bz; sg[ 7*SG_STRIDE+t]=a7+bz;
      sg[ 8*SG_STRIDE+t]=a8+bz; sg[ 9*SG_STRIDE+t]=a9+bz;
      sg[10*SG_STRIDE+t]=aa+bz; sg[11*SG_STRIDE+t]=ab+bz;
      sg[12*SG_STRIDE+t]=ac+bz; sg[13*SG_STRIDE+t]=ad+bz;
      sg[14*SG_STRIDE+t]=ae+bz; sg[15*SG_STRIDE+t]=af+bz;
    }
    __syncthreads();

    // ---- attention phase: warp w -> batch b ----
    const float* gz   = sg + w*SG_STRIDE;
    const float* gaz  = gz + 98;
    const float* gacz = gz + 227;
    const float* gc   = gz + 356;

    float z0  = z[b*ND+lane],   z1  = z[b*ND+32+lane];
    float a0  = az[b*ND+lane],  a1  = az[b*ND+32+lane];
    float c0  = acz[b*ND+lane], c1  = acz[b*ND+32+lane];

    float d_z2   = wsum(z0*z0 + z1*z1);
    float d_zaz  = wsum(z0*a0 + z1*a1);
    float d_az2  = wsum(a0*a0 + a1*a1);
    float d_zacz = wsum(z0*c0 + z1*c1);
    float d_acz2 = wsum(c0*c0 + c1*c1);
    float d_zy1  = wsum(z0*gaz[lane]     + z1*gaz[32+lane]);
    float d_zy2  = wsum(z0*gacz[lane]    + z1*gacz[32+lane]);
    float d_cy3  = wsum(ce0*gaz[64+lane] + ce1*gaz[96+lane]);
    float d_cy4  = wsum(ce0*gacz[64+lane]+ ce1*gacz[96+lane]);

    float s0, t0, s1 = -1e30f, t1 = 0.f;
    {
      int tok = lane;
      if (tok == 0){
        s0 = (d_zy1 + gz[96] + gaz[128])*0.0625f - (d_z2 - 2.f*d_zaz + d_az2);
        t0 = d_cy3 + gc[48];
      } else if (tok == 1){
        s0 = (d_zy2 + gz[97] + gacz[128])*0.0625f - (d_z2 - 2.f*d_zacz + d_acz2);
        t0 = d_cy4 + gc[49];
      } else if (tok < 18){
        int k = tok-2; float aw = arw[b*NKA+k];
        s0 = aw*gz[k]*0.0625f - (d_z2 - 2.f*gz[48+k] + g_aan2[k]);
        t0 = aw*gc[k];
      } else {
        int k = tok-18; float cw = rw[b*NK+k];
        s0 = cw*gz[16+k]*0.0625f - (d_z2 - 2.f*gz[64+k] + g_an2[k]);
        t0 = cw*gc[16+k];
      }
    }
    if (lane < 18){
      int k = lane + 14;     // token lane+32 = chart k = lane+14
      float cw = rw[b*NK+k];
      s1 = cw*gz[16+k]*0.0625f - (d_z2 - 2.f*gz[64+k] + g_an2[k]);
      t1 = cw*gc[16+k];
    }

    float m = wmax(fmaxf(s0, s1));
    float ex0 = __expf(s0 - m);
    float ex1 = (lane < 18) ? __expf(s1 - m) : 0.f;
    float den = wsum(ex0 + ex1);
    float num = wsum(ex0*t0 + ex1*t1);
    if (!lane) out[b] = g_inv_sigma * num / den + fb;
  }

  // ---- generation reset: last block to finish zeroes the flags ----
  __threadfence();
  if (threadIdx.x == 0){
    int old = atomicAdd(&g_f3, 1);
    if (old == NBLK_TOT-1){
      g_f1 = 0; g_f2 = 0;
      __threadfence();
      g_f3 = 0;
    }
  }
}

// =============== launch ===============
extern "C" void kernel_launch(void* const* d_in, const int* in_sizes, int n_in,
                              void* d_out, int out_size)
{
  const float* z     =(const float*)d_in[0];
  const float* rw    =(const float*)d_in[1];
  const float* az    =(const float*)d_in[2];
  const float* arw   =(const float*)d_in[3];
  const float* acz   =(const float*)d_in[4];
  const float* ctrl  =(const float*)d_in[5];
  const float* ecov  =(const float*)d_in[6];
  const float* cemb  =(const float*)d_in[7];
  const float* canch =(const float*)d_in[8];
  const float* acemb =(const float*)d_in[9];
  const float* acanch=(const float*)d_in[10];
  const float* zW    =(const float*)d_in[11];
  const float* zb    =(const float*)d_in[12];
  const float* latW  =(const float*)d_in[13];
  const float* latb  =(const float*)d_in[14];
  const float* codeW =(const float*)d_in[15];
  const float* codeb =(const float*)d_in[16];
  const float* Wq    =(const float*)d_in[17];
  const float* Wk    =(const float*)d_in[18];
  const float* Wv    =(const float*)d_in[19];
  const float* Wo    =(const float*)d_in[20];
  const float* formW =(const float*)d_in[21];
  const float* formb =(const float*)d_in[22];
  float* out = (float*)d_out;

  fused_kernel<<<NBLK_TOT,512>>>(z,rw,az,arw,acz,ctrl,ecov,cemb,canch,acemb,acanch,
                                 zW,zb,latW,latb,codeW,codeb,Wq,Wk,Wv,Wo,formW,formb,out);
}

// round 15
// speedup vs baseline: 1.0365x; 1.0365x over previous
#include <cuda_runtime.h>
#include <cuda_bf16.h>

#define NB  4096
#define ND  64
#define NDM 256
#define NK  32
#define NKA 16
#define NC  160   // M4 row stride; active cols per y: 98,129,129,50

#define NBLK_P   138
#define NBLK_P2S 28
#define NGF_UNIT 256
#define NBLK_TOT 296   // exactly one wave at 2 blocks/SM on 148 SMs

// ----- device scratch -----
__device__ __align__(16) float g_M5[5*ND*NDM];   // Zq, Lk, Lv, Ck, Cv
__device__ __align__(16) float g_B6[5*NDM];      // bq, bLk, bLv, bCk, bCv
__device__ __align__(16) float g_KC[NK*NDM], g_VC[NK*NDM];
__device__ __align__(16) float g_AKC[NKA*NDM], g_AVC[NKA*NDM];
__device__ float g_an2[NK], g_aan2[NKA];
__device__ __align__(16) float g_M2T2[ND*NDM];   // (Wo@form_W)^T : [d][j]
__device__ __align__(16) float g_G[ND*ND];       // form_W^T form_W
__device__ float g_inv_sigma;
__device__ __align__(16) float g_M4[4*ND*NC];    // folded GEMM matrices
__device__ __align__(16) float g_bz[4*NC];

// flag barriers + work counter (zero-init at load; reset by last block each launch)
__device__ volatile int g_f1;
__device__ volatile int g_f2;
__device__ int g_ctr;
__device__ int g_f3;

__device__ __forceinline__ float wsum(float v){
  #pragma unroll
  for(int o=16;o>0;o>>=1) v += __shfl_xor_sync(0xffffffffu,v,o);
  return v;
}
__device__ __forceinline__ float wmax(float v){
  #pragma unroll
  for(int o=16;o>0;o>>=1) v = fmaxf(v,__shfl_xor_sync(0xffffffffu,v,o));
  return v;
}
__device__ __forceinline__ float dot256(const float* __restrict__ A,
                                        const float* __restrict__ B, int lane){
  float4 a0 = *(const float4*)(A + lane*8);
  float4 a1 = *(const float4*)(A + lane*8 + 4);
  float4 b0 = *(const float4*)(B + lane*8);
  float4 b1 = *(const float4*)(B + lane*8 + 4);
  float s = a0.x*b0.x + a0.y*b0.y + a0.z*b0.z + a0.w*b0.w
          + a1.x*b1.x + a1.y*b1.y + a1.z*b1.z + a1.w*b1.w;
  return wsum(s);
}
__device__ __forceinline__ void spin_wait(volatile int* f, int target){
  if (threadIdx.x == 0){ while (*f < target) __nanosleep(128); }
  __syncthreads();
}
__device__ __forceinline__ void signal(volatile int* f){
  __syncthreads();
  __threadfence();
  if (threadIdx.x == 0) atomicAdd((int*)f, 1);
}

#define SG_STRIDE 416   // gf col offsets: y0=0 (98), y1=98 (129), y2=227 (129), y3=356 (50)

// ================= persistent fused kernel =================
__global__ __launch_bounds__(512, 2) void fused_kernel(
  const float* __restrict__ z,    const float* __restrict__ rw,
  const float* __restrict__ az,   const float* __restrict__ arw,
  const float* __restrict__ acz,  const float* __restrict__ ctrl,
  const float* __restrict__ ecov, const float* __restrict__ cemb,
  const float* __restrict__ canch,const float* __restrict__ acemb,
  const float* __restrict__ acanch,
  const float* __restrict__ zW,   const float* __restrict__ zb,
  const float* __restrict__ latW, const float* __restrict__ latb,
  const float* __restrict__ codeW,const float* __restrict__ codeb,
  const float* __restrict__ Wq,   const float* __restrict__ Wk,
  const float* __restrict__ Wv,   const float* __restrict__ Wo,
  const float* __restrict__ formW,const float* __restrict__ formb,
  float* __restrict__ out)
{
  __shared__ __align__(16) float su[12032];      // 47.0 KB union
  __shared__ int s_u;
  const int bid = blockIdx.x;
  const int t = threadIdx.x;
  const int w = t>>5, lane = t&31;

  if (bid < NBLK_P){
    // ================= P path (verbatim R13) =================
    int blk = bid;
    float* As = su;            // [h][r*65+kk], 2x2080
    float* Bs = su + 4160;     // [h][kk*36+c], 2x2304
    if (blk < 132){
      int g, m0, n0;
      if (blk < 80){ g = blk>>4; int s = blk&15; m0=(s>>3)*32; n0=(s&7)*32; }
      else if (blk < 112){ g = 5 + ((blk-80)>>4); int s=(blk-80)&15; m0=(s>>3)*32; n0=(s&7)*32; }
      else if (blk < 128){ int s=blk-112; g=7; m0=(s>>1)*32; n0=(s&1)*32; }
      else { int s=blk-128; g=8; m0=(s>>1)*32; n0=(s&1)*32; }

      const float* Bm = (g==0)? Wq : (g==1||g==2||g==5)? Wk : (g>=7)? formW : Wv;
      const int ldb = (g>=7)? 64 : 256;

      const int h = w>>3, wi = w&7;
      const int r2 = t>>4, kg = (t&15)*4;
      const int kkB = t>>3, c4 = (t&7)*4;

      const float* Ap = cemb; bool avalid = true;
      if (g != 8){
        int grow = m0 + r2;
        if (g==0) Ap = zW + grow*256;
        else if (g==1||g==3) Ap = latW + grow*256;
        else if (g==2||g==4) Ap = codeW + grow*256;
        else if (g==7) Ap = Wo + grow*256;
        else {
          if (grow < 32) Ap = cemb + grow*256;
          else if (grow < 48) Ap = acemb + (grow-32)*256;
          else avalid = false;
        }
      }

      float4 apf[2], bpf[2]; float apf_s[2][4];

      auto loadAB = [&](int s){
        #pragma unroll
        for (int hh=0; hh<2; hh++){
          int base = hh*128 + s*64;
          if (g==8){
            #pragma unroll
            for (int p=0;p<4;p++){
              int idx = t + p*512; int kk = idx>>5, r = idx&31;
              apf_s[hh][p] = formW[(base+kk)*64 + m0 + r];
            }
          } else {
            apf[hh] = avalid ? *(const float4*)(Ap + base + kg) : make_float4(0,0,0,0);
          }
          bpf[hh] = *(const float4*)(Bm + (size_t)(base+kkB)*ldb + n0 + c4);
        }
      };
      auto storeAB = [&](){
        #pragma unroll
        for (int hh=0; hh<2; hh++){
          if (g==8){
            #pragma unroll
            for (int p=0;p<4;p++){
              int idx = t + p*512; int kk = idx>>5, r = idx&31;
              As[hh*2080 + r*65+kk] = apf_s[hh][p];
            }
          } else {
            float* a = As + hh*2080 + r2*65 + kg;
            a[0]=apf[hh].x; a[1]=apf[hh].y; a[2]=apf[hh].z; a[3]=apf[hh].w;
          }
          *(float4*)(Bs + hh*2304 + kkB*36 + c4) = bpf[hh];
        }
      };

      float4 acc = make_float4(0.f,0.f,0.f,0.f);
      auto compute = [&](){
        const float* Ah = As + h*2080;
        const float* Bh = Bs + h*2304;
        #pragma unroll 8
        for (int kk=0;kk<64;kk++){
          float av = Ah[lane*65+kk];
          float4 bv = *(const float4*)(Bh + kk*36 + wi*4);
          acc.x += av*bv.x; acc.y += av*bv.y; acc.z += av*bv.z; acc.w += av*bv.w;
        }
      };

      loadAB(0); storeAB(); __syncthreads();
      loadAB(1);
      compute(); __syncthreads();
      storeAB(); __syncthreads();
      compute();

      __syncthreads();
      float* red = su;           // 2048 floats [h][c][r]
      red[h*1024 + (wi*4+0)*32 + lane] = acc.x;
      red[h*1024 + (wi*4+1)*32 + lane] = acc.y;
      red[h*1024 + (wi*4+2)*32 + lane] = acc.z;
      red[h*1024 + (wi*4+3)*32 + lane] = acc.w;
      __syncthreads();
      #pragma unroll
      for (int ee=0; ee<2; ee++){
        int e = t + ee*512;
        float val = red[e] + red[1024+e];
        int c = e>>5, r = e&31;
        int grow = m0 + r, gcol = n0 + c;
        if (g<=4){
          const int off[5] = {0,1,3,2,4};   // Zq,Lk,Ck,Lv,Cv slot order
          g_M5[off[g]*(ND*NDM) + grow*NDM + gcol] = val;
        } else if (g<=6){
          if (grow < 48){
            float* C = (grow<32) ? ((g==5)? g_KC : g_VC) + grow*NDM + gcol
                                 : ((g==5)? g_AKC : g_AVC) + (grow-32)*NDM + gcol;
            *C = val;
          }
        } else if (g==7){
          g_M2T2[gcol*NDM + grow] = val;
        } else {
          g_G[grow*ND + gcol] = val;
        }
      }
    } else if (blk < 137){        // folded bias vectors, split-K halves
      int bb = blk - 132;
      const float* vv = (bb==0)? zb : (bb<3 ? latb : codeb);
      const float* Bm = (bb==0)? Wq : ((bb==1||bb==3)? Wk : Wv);
      float* sh = su;
      int c = t & 255, hh = t >> 8;
      float s = 0.f;
      #pragma unroll 16
      for (int i=hh*128; i<hh*128+128; i++) s += vv[i]*Bm[i*NDM+c];
      sh[t] = s;
      __syncthreads();
      if (t < 256) g_B6[bb*NDM + t] = sh[t] + sh[256+t];
    } else {                      // anchor norms
      if (t < 32) {
        float s=0.f;
        for (int i=0;i<ND;i++){ float v=canch[t*ND+i]; s+=v*v; }
        g_an2[t]=s;
      } else if (t < 48) {
        int k=t-32; float s=0.f;
        for (int i=0;i<ND;i++){ float v=acanch[k*ND+i]; s+=v*v; }
        g_aan2[k]=s;
      }
    }
    signal(&g_f1);
  }
  else if (bid < NBLK_P + NBLK_P2S){
    // ================= P2S path (verbatim R13) =================
    spin_wait(&g_f1, NBLK_P);
    __threadfence();
    int blk = bid - NBLK_P;
    float* sm = su;
    const float* Zq = g_M5;
    const float* Lk = g_M5 + 1*ND*NDM;
    const float* Lv = g_M5 + 2*ND*NDM;
    const float* Ck = g_M5 + 3*ND*NDM;
    const float* Cv = g_M5 + 4*ND*NDM;

    if (blk == 0){
      float* sA = sm; float* sB = sm + 4096; float* sv = sm + 8192;
      #pragma unroll
      for (int r=0;r<8;r++) sA[t + r*512] = g_G[t + r*512];
      __syncthreads();
      const int pr = (t>>4)*2, pc = (t&15)*4;
      for (int sq=0; sq<3; sq++){
        float4 ac0=make_float4(0,0,0,0), ac1=ac0;
        #pragma unroll 4
        for (int q=0;q<64;q++){
          float4 bv = *(const float4*)(sA + q*64 + pc);
          float a0=sA[pr*64+q], a1=sA[(pr+1)*64+q];
          ac0.x+=a0*bv.x; ac0.y+=a0*bv.y; ac0.z+=a0*bv.z; ac0.w+=a0*bv.w;
          ac1.x+=a1*bv.x; ac1.y+=a1*bv.y; ac1.z+=a1*bv.z; ac1.w+=a1*bv.w;
        }
        *(float4*)(sB + (pr+0)*64 + pc) = ac0;
        *(float4*)(sB + (pr+1)*64 + pc) = ac1;
        __syncthreads();
        #pragma unroll
        for (int k=0;k<2;k++) ((float4*)sA)[t*2+k] = ((const float4*)sB)[t*2+k];
        __syncthreads();
      }
      if (t < 32){
        sv[lane]=1.f; sv[lane+32]=1.f; __syncwarp();
        for (int it=0; it<10; it++){
          float y0=0.f, y1=0.f;
          for (int q=0;q<64;q++){ float vq=sv[q]; y0+=sA[q*64+lane]*vq; y1+=sA[q*64+32+lane]*vq; }
          float rn = rsqrtf(wsum(y0*y0+y1*y1));
          sv[lane]=y0*rn; sv[lane+32]=y1*rn; __syncwarp();
        }
        float p0=0.f, p1=0.f;     // Rayleigh on ORIGINAL G
        for (int q=0;q<64;q++){ float vq=sv[q]; p0+=g_G[lane*64+q]*vq; p1+=g_G[(lane+32)*64+q]*vq; }
        float lam = wsum(p0*sv[lane]+p1*sv[lane+32]);
        if (!lane) g_inv_sigma = 1.f/fmaxf(sqrtf(fmaxf(lam,0.f)),1e-8f);
      }
    } else if (blk == 1){
      for (int idx=t; idx<3072; idx+=512){
        int i = idx/48, c = idx - i*48;
        g_M4[i*NC + 48 + c] = (c<16)? acanch[c*ND+i] : canch[(c-16)*ND+i];
      }
    } else if (blk == 2){
      for (int idx=t; idx<4*NC; idx+=512) g_bz[idx] = 0.f;
      __syncthreads();
      for (int j=w; j<178; j+=16){
        if (j < 48){
          const float* B = (j<16)? g_AKC+j*NDM : g_KC+(j-16)*NDM;
          float s = dot256(g_B6, B, lane);
          if (!lane) g_bz[j] = s;
        } else if (j < 50){
          const float* B = (j==48)? g_B6+NDM : g_B6+3*NDM;
          float s = dot256(g_B6, B, lane);
          if (!lane) g_bz[(j==48)?96:97] = s;
        } else if (j < 114){
          int i = j-50;
          float s = dot256(Zq+i*NDM, g_B6+NDM, lane);
          if (!lane) g_M4[i*NC+96] = s;
        } else {
          int i = j-114;
          float s = dot256(Zq+i*NDM, g_B6+3*NDM, lane);
          if (!lane) g_M4[i*NC+97] = s;
        }
      }
    } else if (blk == 3){
      for (int j=w; j<256; j+=16){
        float s; int r, col;
        if (j < 64)      { s = dot256(Lk+j*NDM,          g_B6,       lane); r=64+j;        col=128; }
        else if (j<128)  { s = dot256(Ck+(j-64)*NDM,     g_B6,       lane); r=128+(j-64);  col=128; }
        else if (j<192)  { s = dot256(g_M2T2+(j-128)*NDM,g_B6+2*NDM, lane); r=192+(j-128); col=48;  }
        else             { s = dot256(g_M2T2+(j-192)*NDM,g_B6+4*NDM, lane); r=192+(j-192); col=49;  }
        if (!lane) g_M4[r*NC+col] = s;
      }
    } else {
      // tile blocks 4..27: split-K 32x32 stage-2 GEMM tiles
      int tid2 = blk - 4;
      int typ = tid2>>2, sub = tid2&3, m0 = (sub>>1)*32, n0 = (sub&1)*32;
      const float* Ab; int orow, ocol, maxc, bsel;
      switch(typ){
        case 0: Ab=Zq;     orow=0;   ocol=0;  maxc=48; bsel=0; break;
        case 1: Ab=Lk;     orow=64;  ocol=0;  maxc=64; bsel=1; break;
        case 2: Ab=Lv;     orow=64;  ocol=64; maxc=64; bsel=2; break;
        case 3: Ab=Ck;     orow=128; ocol=0;  maxc=64; bsel=1; break;
        case 4: Ab=Cv;     orow=128; ocol=64; maxc=64; bsel=2; break;
        default:Ab=g_M2T2; orow=192; ocol=0;  maxc=48; bsel=3; break;
      }
      float* As0 = sm;
      float* Bs0 = sm + 4160;
      const int h = w>>3, wi = w&7;
      const int r2 = t>>4, kg = (t&15)*4;
      const int cB = t>>4, kg2 = (t&15)*4;
      const float* Ap = Ab + (m0+r2)*NDM;
      int cglob = n0 + cB;
      const float* Bp;
      if (bsel==0)      Bp = (cglob<16)? g_AKC + cglob*NDM : (cglob<48)? g_KC + (cglob-16)*NDM : g_AKC;
      else if (bsel==1) Bp = g_M5 + cglob*NDM;
      else if (bsel==2) Bp = g_M2T2 + cglob*NDM;
      else              Bp = (cglob<16)? g_AVC + cglob*NDM : (cglob<48)? g_VC + (cglob-16)*NDM : g_AVC;

      float4 apf[2], bpf[2];
      auto loadAB = [&](int s){
        #pragma unroll
        for (int hh=0; hh<2; hh++){
          int base = hh*128 + s*64;
          apf[hh] = *(const float4*)(Ap + base + kg);
          bpf[hh] = *(const float4*)(Bp + base + kg2);
        }
      };
      auto storeAB = [&](){
        #pragma unroll
        for (int hh=0; hh<2; hh++){
          float* a = As0 + hh*2080 + r2*65 + kg;
          a[0]=apf[hh].x; a[1]=apf[hh].y; a[2]=apf[hh].z; a[3]=apf[hh].w;
          const float* bv = (const float*)&bpf[hh];
          #pragma unroll
          for (int i=0;i<4;i++){
            int kk = kg2+i;
            Bs0[hh*2304 + kk*36 + (cB ^ (kk&28))] = bv[i];
          }
        }
      };

      float4 acc = make_float4(0.f,0.f,0.f,0.f);
      auto compute = [&](){
        const float* Ah = As0 + h*2080;
        const float* Bh = Bs0 + h*2304;
        #pragma unroll 8
        for (int kk=0;kk<64;kk++){
          float av = Ah[lane*65+kk];
          float4 bv = *(const float4*)(Bh + kk*36 + ((wi*4) ^ (kk&28)));
          acc.x += av*bv.x; acc.y += av*bv.y; acc.z += av*bv.z; acc.w += av*bv.w;
        }
      };

      loadAB(0); storeAB(); __syncthreads();
      loadAB(1);
      compute(); __syncthreads();
      storeAB(); __syncthreads();
      compute();

      __syncthreads();
      float* red = sm;             // 2048 floats [h][c][r]
      red[h*1024 + (wi*4+0)*32 + lane] = acc.x;
      red[h*1024 + (wi*4+1)*32 + lane] = acc.y;
      red[h*1024 + (wi*4+2)*32 + lane] = acc.z;
      red[h*1024 + (wi*4+3)*32 + lane] = acc.w;
      __syncthreads();
      #pragma unroll
      for (int ee=0; ee<2; ee++){
        int e = t + ee*512;
        float val = red[e] + red[1024+e];
        int c = e>>5, r = e&31;
        int j0 = n0 + c;
        if (j0 < maxc) g_M4[(orow+m0+r)*NC + ocol + j0] = val;
      }
    }
    signal(&g_f2);
  }

  // ================= GF phase: all 296 blocks, dynamic units =================
  spin_wait(&g_f2, NBLK_P2S);
  __threadfence();

  float* xsT = su;              // [y][i][bb], stride 20 (5120 floats)
  float* sg  = su + 5120;       // [bat][col] (6656 floats)

  while (true){
    __syncthreads();            // protect su reuse across iterations / prior phases
    if (t == 0) s_u = atomicAdd(&g_ctr, 1);
    __syncthreads();
    int u = s_u;
    if (u >= NGF_UNIT) break;

    const int b0 = u*16;
    const int b = b0 + w;

    // preamble: xsT tiles + ceff
    for (int idx=t; idx<3072; idx+=512){
      int y = idx>>10, r = idx&1023, bb = r>>6, i = r&63;
      const float* X = (y==0)? z : (y==1)? az : acz;
      xsT[(y*64+i)*20 + bb] = X[(b0+bb)*ND + i];
    }
    float e0=ecov[b*ND+lane], e1=ecov[b*ND+32+lane];
    float c0g=ctrl[b*ND+lane], c1g=ctrl[b*ND+32+lane];
    float ee = wsum(e0*e0+e1*e1);
    float ec = wsum(e0*c0g+e1*c1g);
    float kk = (ee > 1e-8f) ? ec/fmaxf(ee,1e-8f) : 0.f;
    float ce0 = c0g - kk*e0, ce1 = c1g - kk*e1;
    float fb = wsum(formb[lane]*ce0 + formb[lane+32]*ce1);
    xsT[(3*64+lane)*20 + w]    = ce0;
    xsT[(3*64+32+lane)*20 + w] = ce1;
    __syncthreads();

    // GEMM phase
    if (t < 406){
      int y, col;
      if (t<98){y=0;col=t;} else if (t<227){y=1;col=t-98;}
      else if (t<356){y=2;col=t-227;} else {y=3;col=t-356;}
      const float* M  = g_M4 + (y*ND)*NC + col;
      const float* xb = xsT + (y*64)*20;
      float a0=0,a1=0,a2=0,a3=0,a4=0,a5=0,a6=0,a7=0,a8=0,a9=0,aa=0,ab=0,ac=0,ad=0,ae=0,af=0;
      #pragma unroll 4
      for (int i=0;i<64;i++){
        float mv = M[(size_t)i*NC];
        const float4* x4 = (const float4*)(xb + i*20);
        float4 v0=x4[0], v1=x4[1], v2=x4[2], v3=x4[3];
        a0+=mv*v0.x; a1+=mv*v0.y; a2+=mv*v0.z; a3+=mv*v0.w;
        a4+=mv*v1.x; a5+=mv*v1.y; a6+=mv*v1.z; a7+=mv*v1.w;
        a8+=mv*v2.x; a9+=mv*v2.y; aa+=mv*v2.z; ab+=mv*v2.w;
        ac+=mv*v3.x; ad+=mv*v3.y; ae+=mv*v3.z; af+=mv*v3.w;
      }
      float bz = g_bz[y*NC+col];
      sg[ 0*SG_STRIDE+t]=a0+bz; sg[ 1*SG_STRIDE+t]=a1+bz;
      sg[ 2*SG_STRIDE+t]=a2+bz; sg[ 3*SG_STRIDE+t]=a3+bz;
      sg[ 4*SG_STRIDE+t]=a4+bz; sg[ 5*SG_STRIDE+t]=a5+bz;
      sg[ 6*SG_STRIDE+t]=a6+bz; sg[ 7*SG_STRIDE+t]=a7+bz;
      sg[ 8*SG_STRIDE+t]=a8+bz; sg[ 9*SG_STRIDE+t]=a9+bz;
      sg[10*SG_STRIDE+t]=aa+bz; sg[11*SG_STRIDE+t]=ab+bz;
      sg[12*SG_STRIDE+t]=ac+bz; sg[13*SG_STRIDE+t]=ad+bz;
      sg[14*SG_STRIDE+t]=ae+bz; sg[15*SG_STRIDE+t]=af+bz;
    }
    __syncthreads();

    // attention phase: warp w -> batch b
    const float* gz   = sg + w*SG_STRIDE;
    const float* gaz  = gz + 98;
    const float* gacz = gz + 227;
    const float* gc   = gz + 356;

    float z0  = z[b*ND+lane],   z1  = z[b*ND+32+lane];
    float a0  = az[b*ND+lane],  a1  = az[b*ND+32+lane];
    float c0  = acz[b*ND+lane], c1  = acz[b*ND+32+lane];

    float d_z2   = wsum(z0*z0 + z1*z1);
    float d_zaz  = wsum(z0*a0 + z1*a1);
    float d_az2  = wsum(a0*a0 + a1*a1);
    float d_zacz = wsum(z0*c0 + z1*c1);
    float d_acz2 = wsum(c0*c0 + c1*c1);
    float d_zy1  = wsum(z0*gaz[lane]     + z1*gaz[32+lane]);
    float d_zy2  = wsum(z0*gacz[lane]    + z1*gacz[32+lane]);
    float d_cy3  = wsum(ce0*gaz[64+lane] + ce1*gaz[96+lane]);
    float d_cy4  = wsum(ce0*gacz[64+lane]+ ce1*gacz[96+lane]);

    float s0, t0, s1 = -1e30f, t1 = 0.f;
    {
      int tok = lane;
      if (tok == 0){
        s0 = (d_zy1 + gz[96] + gaz[128])*0.0625f - (d_z2 - 2.f*d_zaz + d_az2);
        t0 = d_cy3 + gc[48];
      } else if (tok == 1){
        s0 = (d_zy2 + gz[97] + gacz[128])*0.0625f - (d_z2 - 2.f*d_zacz + d_acz2);
        t0 = d_cy4 + gc[49];
      } else if (tok < 18){
        int k = tok-2; float aw = arw[b*NKA+k];
        s0 = aw*gz[k]*0.0625f - (d_z2 - 2.f*gz[48+k] + g_aan2[k]);
        t0 = aw*gc[k];
      } else {
        int k = tok-18; float cw = rw[b*NK+k];
        s0 = cw*gz[16+k]*0.0625f - (d_z2 - 2.f*gz[64+k] + g_an2[k]);
        t0 = cw*gc[16+k];
      }
    }
    if (lane < 18){
      int k = lane + 14;     // token lane+32 = chart k = lane+14
      float cw = rw[b*NK+k];
      s1 = cw*gz[16+k]*0.0625f - (d_z2 - 2.f*gz[64+k] + g_an2[k]);
      t1 = cw*gc[16+k];
    }

    float m = wmax(fmaxf(s0, s1));
    float ex0 = __expf(s0 - m);
    float ex1 = (lane < 18) ? __expf(s1 - m) : 0.f;
    float den = wsum(ex0 + ex1);
    float num = wsum(ex0*t0 + ex1*t1);
    if (!lane) out[b] = g_inv_sigma * num / den + fb;
  }

  // ---- generation reset (all blocks have exited the work loop) ----
  __threadfence();
  if (threadIdx.x == 0){
    int old = atomicAdd(&g_f3, 1);
    if (old == NBLK_TOT-1){
      g_f1 = 0; g_f2 = 0; g_ctr = 0;
      __threadfence();
      g_f3 = 0;
    }
  }
}

// =============== launch ===============
extern "C" void kernel_launch(void* const* d_in, const int* in_sizes, int n_in,
                              void* d_out, int out_size)
{
  const float* z     =(const float*)d_in[0];
  const float* rw    =(const float*)d_in[1];
  const float* az    =(const float*)d_in[2];
  const float* arw   =(const float*)d_in[3];
  const float* acz   =(const float*)d_in[4];
  const float* ctrl  =(const float*)d_in[5];
  const float* ecov  =(const float*)d_in[6];
  const float* cemb  =(const float*)d_in[7];
  const float* canch =(const float*)d_in[8];
  const float* acemb =(const float*)d_in[9];
  const float* acanch=(const float*)d_in[10];
  const float* zW    =(const float*)d_in[11];
  const float* zb    =(const float*)d_in[12];
  const float* latW  =(const float*)d_in[13];
  const float* latb  =(const float*)d_in[14];
  const float* codeW =(const float*)d_in[15];
  const float* codeb =(const float*)d_in[16];
  const float* Wq    =(const float*)d_in[17];
  const float* Wk    =(const float*)d_in[18];
  const float* Wv    =(const float*)d_in[19];
  const float* Wo    =(const float*)d_in[20];
  const float* formW =(const float*)d_in[21];
  const float* formb =(const float*)d_in[22];
  float* out = (float*)d_out;

  fused_kernel<<<NBLK_TOT,512>>>(z,rw,az,arw,acz,ctrl,ecov,cemb,canch,acemb,acanch,
                                 zW,zb,latW,latb,codeW,codeb,Wq,Wk,Wv,Wo,formW,formb,out);
}

// round 16
// speedup vs baseline: 1.1390x; 1.0988x over previous
#include <cuda_runtime.h>
#include <cuda_bf16.h>

#define NB  4096
#define ND  64
#define NDM 256
#define NK  32
#define NKA 16
#define NC  160   // M4 row stride; active cols per y: 98,129,129,50

// ----- device scratch -----
__device__ __align__(16) float g_M5[5*ND*NDM];   // Zq, Lk, Lv, Ck, Cv
__device__ __align__(16) float g_B6[5*NDM];      // bq, bLk, bLv, bCk, bCv
__device__ __align__(16) float g_KC[NK*NDM], g_VC[NK*NDM];
__device__ __align__(16) float g_AKC[NKA*NDM], g_AVC[NKA*NDM];
__device__ float g_an2[NK], g_aan2[NKA];
__device__ __align__(16) float g_M2T2[ND*NDM];   // (Wo@form_W)^T : [d][j]
__device__ __align__(16) float g_G[ND*ND];       // form_W^T form_W
__device__ float g_inv_sigma;
__device__ __align__(16) float g_M4[4*ND*NC];    // folded GEMM matrices
__device__ __align__(16) float g_bz[4*NC];

typedef unsigned long long ull;

__device__ __forceinline__ float wsum(float v){
  #pragma unroll
  for(int o=16;o>0;o>>=1) v += __shfl_xor_sync(0xffffffffu,v,o);
  return v;
}
__device__ __forceinline__ float wmax(float v){
  #pragma unroll
  for(int o=16;o>0;o>>=1) v = fmaxf(v,__shfl_xor_sync(0xffffffffu,v,o));
  return v;
}
__device__ __forceinline__ float dot256(const float* __restrict__ A,
                                        const float* __restrict__ B, int lane){
  float4 a0 = *(const float4*)(A + lane*8);
  float4 a1 = *(const float4*)(A + lane*8 + 4);
  float4 b0 = *(const float4*)(B + lane*8);
  float4 b1 = *(const float4*)(B + lane*8 + 4);
  float s = a0.x*b0.x + a0.y*b0.y + a0.z*b0.z + a0.w*b0.w
          + a1.x*b1.x + a1.y*b1.y + a1.z*b1.z + a1.w*b1.w;
  return wsum(s);
}
// packed fp32x2 helpers
__device__ __forceinline__ ull bcast2(float v){
  ull r;
  asm("mov.b64 %0, {%1, %1};" : "=l"(r) : "r"(__float_as_uint(v)));
  return r;
}
__device__ __forceinline__ void fma2(ull& acc, ull a, ull b){
  asm("fma.rn.f32x2 %0, %1, %2, %0;" : "+l"(acc) : "l"(a), "l"(b));
}
__device__ __forceinline__ float2 unpack2(ull v){
  unsigned int lo, hi;
  asm("mov.b64 {%0, %1}, %2;" : "=r"(lo), "=r"(hi) : "l"(v));
  return make_float2(__uint_as_float(lo), __uint_as_float(hi));
}

// =============== P1: stage-1 folds — split-K 32x32 tiles (f32x2 core) ===============
__global__ __launch_bounds__(512) void p_kernel(
  const float* __restrict__ zW,   const float* __restrict__ latW, const float* __restrict__ codeW,
  const float* __restrict__ Wq,   const float* __restrict__ Wk,   const float* __restrict__ Wv,
  const float* __restrict__ Wo,   const float* __restrict__ cemb, const float* __restrict__ acemb,
  const float* __restrict__ formW,const float* __restrict__ zb,   const float* __restrict__ latb,
  const float* __restrict__ codeb,const float* __restrict__ canch,const float* __restrict__ acanch)
{
  __shared__ float As[2][2080];                 // [h][r*65 + kk]
  __shared__ __align__(16) float Bs[2][2304];   // [h][kk*36 + c]
  int blk = blockIdx.x;
  const int t = threadIdx.x;
  const int w = t>>5, lane = t&31;

  if (blk < 132){
    int g, m0, n0;
    if (blk < 80){ g = blk>>4; int s = blk&15; m0=(s>>3)*32; n0=(s&7)*32; }
    else if (blk < 112){ g = 5 + ((blk-80)>>4); int s=(blk-80)&15; m0=(s>>3)*32; n0=(s&7)*32; }
    else if (blk < 128){ int s=blk-112; g=7; m0=(s>>1)*32; n0=(s&1)*32; }
    else { int s=blk-128; g=8; m0=(s>>1)*32; n0=(s&1)*32; }

    const float* Bm = (g==0)? Wq : (g==1||g==2||g==5)? Wk : (g>=7)? formW : Wv;
    const int ldb = (g>=7)? 64 : 256;

    const int h = w>>3, wi = w&7;
    const int r2 = t>>4, kg = (t&15)*4;       // A load role
    const int kkB = t>>3, c4 = (t&7)*4;       // B load role

    const float* Ap = cemb; bool avalid = true;
    if (g != 8){
      int grow = m0 + r2;
      if (g==0) Ap = zW + grow*256;
      else if (g==1||g==3) Ap = latW + grow*256;
      else if (g==2||g==4) Ap = codeW + grow*256;
      else if (g==7) Ap = Wo + grow*256;
      else {
        if (grow < 32) Ap = cemb + grow*256;
        else if (grow < 48) Ap = acemb + (grow-32)*256;
        else avalid = false;
      }
    }

    float4 apf[2], bpf[2]; float apf_s[2][4];

    auto loadAB = [&](int s){
      #pragma unroll
      for (int hh=0; hh<2; hh++){
        int base = hh*128 + s*64;
        if (g==8){
          #pragma unroll
          for (int p=0;p<4;p++){
            int idx = t + p*512; int kk = idx>>5, r = idx&31;
            apf_s[hh][p] = formW[(base+kk)*64 + m0 + r];
          }
        } else {
          apf[hh] = avalid ? *(const float4*)(Ap + base + kg) : make_float4(0,0,0,0);
        }
        bpf[hh] = *(const float4*)(Bm + (size_t)(base+kkB)*ldb + n0 + c4);
      }
    };
    auto storeAB = [&](){
      #pragma unroll
      for (int hh=0; hh<2; hh++){
        if (g==8){
          #pragma unroll
          for (int p=0;p<4;p++){
            int idx = t + p*512; int kk = idx>>5, r = idx&31;
            As[hh][r*65+kk] = apf_s[hh][p];
          }
        } else {
          float* a = &As[hh][r2*65+kg];
          a[0]=apf[hh].x; a[1]=apf[hh].y; a[2]=apf[hh].z; a[3]=apf[hh].w;
        }
        *(float4*)(&Bs[hh][kkB*36 + c4]) = bpf[hh];
      }
    };

    ull acc2[2] = {0ull, 0ull};
    auto compute = [&](){
      #pragma unroll 8
      for (int kk=0;kk<64;kk++){
        ull av2 = bcast2(As[h][lane*65+kk]);
        const ull* b2 = (const ull*)(&Bs[h][kk*36 + wi*4]);
        fma2(acc2[0], av2, b2[0]);
        fma2(acc2[1], av2, b2[1]);
      }
    };

    loadAB(0); storeAB(); __syncthreads();
    loadAB(1);                         // prefetch step 1
    compute(); __syncthreads();
    storeAB(); __syncthreads();
    compute();

    float2 p01 = unpack2(acc2[0]);
    float2 p23 = unpack2(acc2[1]);
    // cross-half reduce: red layout [h][c][r] -> conflict-free both sides
    __syncthreads();
    float* red = &As[0][0];            // 2048 floats
    red[h*1024 + (wi*4+0)*32 + lane] = p01.x;
    red[h*1024 + (wi*4+1)*32 + lane] = p01.y;
    red[h*1024 + (wi*4+2)*32 + lane] = p23.x;
    red[h*1024 + (wi*4+3)*32 + lane] = p23.y;
    __syncthreads();
    #pragma unroll
    for (int ee=0; ee<2; ee++){
      int e = t + ee*512;
      float val = red[e] + red[1024+e];
      int c = e>>5, r = e&31;
      int grow = m0 + r, gcol = n0 + c;
      if (g<=4){
        const int off[5] = {0,1,3,2,4};   // Zq,Lk,Ck,Lv,Cv slot order
        g_M5[off[g]*(ND*NDM) + grow*NDM + gcol] = val;
      } else if (g<=6){
        if (grow < 48){
          float* C = (grow<32) ? ((g==5)? g_KC : g_VC) + grow*NDM + gcol
                               : ((g==5)? g_AKC : g_AVC) + (grow-32)*NDM + gcol;
          *C = val;
        }
      } else if (g==7){
        g_M2T2[gcol*NDM + grow] = val;
      } else {
        g_G[grow*ND + gcol] = val;
      }
    }
    return;
  }
  blk -= 132;
  if (blk < 5) {                  // folded bias vectors, split-K halves
    const float* vv = (blk==0)? zb : (blk<3 ? latb : codeb);
    const float* Bm = (blk==0)? Wq : ((blk==1||blk==3)? Wk : Wv);
    float* sh = &As[0][0];
    int c = t & 255, hh = t >> 8;
    float s = 0.f;
    #pragma unroll 16
    for (int i=hh*128; i<hh*128+128; i++) s += vv[i]*Bm[i*NDM+c];
    sh[t] = s;
    __syncthreads();
    if (t < 256) g_B6[blk*NDM + t] = sh[t] + sh[256+t];
    return;
  }
  // anchor norms
  if (t < 32) {
    float s=0.f;
    for (int i=0;i<ND;i++){ float v=canch[t*ND+i]; s+=v*v; }
    g_an2[t]=s;
  } else if (t < 48) {
    int k=t-32; float s=0.f;
    for (int i=0;i<ND;i++){ float v=acanch[k*ND+i]; s+=v*v; }
    g_aan2[k]=s;
  }
}

// =============== P2S: sigma | anchors | vectors | 24 split-K GEMM tiles ===============
__global__ __launch_bounds__(512) void p2s_kernel(
  const float* __restrict__ canch, const float* __restrict__ acanch)
{
  __shared__ __align__(16) float sm[8768];   // sigma(8256) | tiles: As 4160 + Bs 4608
  const int blk = blockIdx.x, t = threadIdx.x, w = t>>5, lane = t&31;
  const float* Zq = g_M5;
  const float* Lk = g_M5 + 1*ND*NDM;
  const float* Lv = g_M5 + 2*ND*NDM;
  const float* Ck = g_M5 + 3*ND*NDM;
  const float* Cv = g_M5 + 4*ND*NDM;

  if (blk == 0){
    // ---- sigma: 3 register-tiled squarings (G^8) + 10 power iters + Rayleigh ----
    float* sA = sm; float* sB = sm + 4096; float* sv = sm + 8192;
    #pragma unroll
    for (int r=0;r<8;r++) sA[t + r*512] = g_G[t + r*512];
    __syncthreads();
    const int pr = (t>>4)*2, pc = (t&15)*4;
    for (int sq=0; sq<3; sq++){
      float4 ac0=make_float4(0,0,0,0), ac1=ac0;
      #pragma unroll 4
      for (int q=0;q<64;q++){
        float4 bv = *(const float4*)(sA + q*64 + pc);
        float a0=sA[pr*64+q], a1=sA[(pr+1)*64+q];
        ac0.x+=a0*bv.x; ac0.y+=a0*bv.y; ac0.z+=a0*bv.z; ac0.w+=a0*bv.w;
        ac1.x+=a1*bv.x; ac1.y+=a1*bv.y; ac1.z+=a1*bv.z; ac1.w+=a1*bv.w;
      }
      *(float4*)(sB + (pr+0)*64 + pc) = ac0;
      *(float4*)(sB + (pr+1)*64 + pc) = ac1;
      __syncthreads();
      #pragma unroll
      for (int k=0;k<2;k++) ((float4*)sA)[t*2+k] = ((const float4*)sB)[t*2+k];
      __syncthreads();
    }
    if (t < 32){
      sv[lane]=1.f; sv[lane+32]=1.f; __syncwarp();
      for (int it=0; it<10; it++){
        float y0=0.f, y1=0.f;
        for (int q=0;q<64;q++){ float vq=sv[q]; y0+=sA[q*64+lane]*vq; y1+=sA[q*64+32+lane]*vq; }
        float rn = rsqrtf(wsum(y0*y0+y1*y1));
        sv[lane]=y0*rn; sv[lane+32]=y1*rn; __syncwarp();
      }
      float p0=0.f, p1=0.f;     // Rayleigh on ORIGINAL G
      for (int q=0;q<64;q++){ float vq=sv[q]; p0+=g_G[lane*64+q]*vq; p1+=g_G[(lane+32)*64+q]*vq; }
      float lam = wsum(p0*sv[lane]+p1*sv[lane+32]);
      if (!lane) g_inv_sigma = 1.f/fmaxf(sqrtf(fmaxf(lam,0.f)),1e-8f);
    }
    return;
  }
  if (blk == 1){                  // anchor columns of y0 (cols 48-95)
    for (int idx=t; idx<3072; idx+=512){
      int i = idx/48, c = idx - i*48;
      g_M4[i*NC + 48 + c] = (c<16)? acanch[c*ND+i] : canch[(c-16)*ND+i];
    }
    return;
  }
  if (blk == 2){                  // g_bz row + u1/u2 columns
    for (int idx=t; idx<4*NC; idx+=512) g_bz[idx] = 0.f;
    __syncthreads();
    for (int j=w; j<178; j+=16){
      if (j < 48){
        const float* B = (j<16)? g_AKC+j*NDM : g_KC+(j-16)*NDM;
        float s = dot256(g_B6, B, lane);
        if (!lane) g_bz[j] = s;
      } else if (j < 50){
        const float* B = (j==48)? g_B6+NDM : g_B6+3*NDM;
        float s = dot256(g_B6, B, lane);
        if (!lane) g_bz[(j==48)?96:97] = s;
      } else if (j < 114){
        int i = j-50;
        float s = dot256(Zq+i*NDM, g_B6+NDM, lane);
        if (!lane) g_M4[i*NC+96] = s;
      } else {
        int i = j-114;
        float s = dot256(Zq+i*NDM, g_B6+3*NDM, lane);
        if (!lane) g_M4[i*NC+97] = s;
      }
    }
    return;
  }
  if (blk == 3){                  // w1,w2 (col 128) and vb3,vb4 (cols 48/49 of y3)
    for (int j=w; j<256; j+=16){
      float s; int r, col;
      if (j < 64)      { s = dot256(Lk+j*NDM,          g_B6,       lane); r=64+j;        col=128; }
      else if (j<128)  { s = dot256(Ck+(j-64)*NDM,     g_B6,       lane); r=128+(j-64);  col=128; }
      else if (j<192)  { s = dot256(g_M2T2+(j-128)*NDM,g_B6+2*NDM, lane); r=192+(j-128); col=48;  }
      else             { s = dot256(g_M2T2+(j-192)*NDM,g_B6+4*NDM, lane); r=192+(j-192); col=49;  }
      if (!lane) g_M4[r*NC+col] = s;
    }
    return;
  }
  // ---- tile blocks 4..27: split-K 32x32 stage-2 GEMM tiles (f32x2 core) ----
  {
    int tid = blk - 4;            // 0..23
    int typ = tid>>2, sub = tid&3, m0 = (sub>>1)*32, n0 = (sub&1)*32;
    const float* Ab; int orow, ocol, maxc, bsel;
    switch(typ){
      case 0: Ab=Zq;     orow=0;   ocol=0;  maxc=48; bsel=0; break;
      case 1: Ab=Lk;     orow=64;  ocol=0;  maxc=64; bsel=1; break;
      case 2: Ab=Lv;     orow=64;  ocol=64; maxc=64; bsel=2; break;
      case 3: Ab=Ck;     orow=128; ocol=0;  maxc=64; bsel=1; break;
      case 4: Ab=Cv;     orow=128; ocol=64; maxc=64; bsel=2; break;
      default:Ab=g_M2T2; orow=192; ocol=0;  maxc=48; bsel=3; break;
    }
    float* As0 = sm;              // [h][r*65+kk], 2x2080
    float* Bs0 = sm + 4160;       // [h][kk*36 + swz(c)], 2x2304
    const int h = w>>3, wi = w&7;
    const int r2 = t>>4, kg = (t&15)*4;     // A role
    const int cB = t>>4, kg2 = (t&15)*4;    // B role (transposed)
    const float* Ap = Ab + (m0+r2)*NDM;
    int cglob = n0 + cB;
    const float* Bp;
    if (bsel==0)      Bp = (cglob<16)? g_AKC + cglob*NDM : (cglob<48)? g_KC + (cglob-16)*NDM : g_AKC;
    else if (bsel==1) Bp = g_M5 + cglob*NDM;
    else if (bsel==2) Bp = g_M2T2 + cglob*NDM;
    else              Bp = (cglob<16)? g_AVC + cglob*NDM : (cglob<48)? g_VC + (cglob-16)*NDM : g_AVC;

    float4 apf[2], bpf[2];
    auto loadAB = [&](int s){
      #pragma unroll
      for (int hh=0; hh<2; hh++){
        int base = hh*128 + s*64;
        apf[hh] = *(const float4*)(Ap + base + kg);
        bpf[hh] = *(const float4*)(Bp + base + kg2);
      }
    };
    auto storeAB = [&](){
      #pragma unroll
      for (int hh=0; hh<2; hh++){
        float* a = As0 + hh*2080 + r2*65 + kg;
        a[0]=apf[hh].x; a[1]=apf[hh].y; a[2]=apf[hh].z; a[3]=apf[hh].w;
        const float* bv = (const float*)&bpf[hh];
        #pragma unroll
        for (int i=0;i<4;i++){
          int kk = kg2+i;
          Bs0[hh*2304 + kk*36 + (cB ^ (kk&28))] = bv[i];
        }
      }
    };

    ull acc2[2] = {0ull, 0ull};
    auto compute = [&](){
      const float* Ah = As0 + h*2080;
      const float* Bh = Bs0 + h*2304;
      #pragma unroll 8
      for (int kk=0;kk<64;kk++){
        ull av2 = bcast2(Ah[lane*65+kk]);
        const ull* b2 = (const ull*)(Bh + kk*36 + ((wi*4) ^ (kk&28)));
        fma2(acc2[0], av2, b2[0]);
        fma2(acc2[1], av2, b2[1]);
      }
    };

    loadAB(0); storeAB(); __syncthreads();
    loadAB(1);
    compute(); __syncthreads();
    storeAB(); __syncthreads();
    compute();

    float2 p01 = unpack2(acc2[0]);
    float2 p23 = unpack2(acc2[1]);
    __syncthreads();
    float* red = sm;               // 2048 floats, layout [h][c][r]
    red[h*1024 + (wi*4+0)*32 + lane] = p01.x;
    red[h*1024 + (wi*4+1)*32 + lane] = p01.y;
    red[h*1024 + (wi*4+2)*32 + lane] = p23.x;
    red[h*1024 + (wi*4+3)*32 + lane] = p23.y;
    __syncthreads();
    #pragma unroll
    for (int ee=0; ee<2; ee++){
      int e = t + ee*512;
      float val = red[e] + red[1024+e];
      int c = e>>5, r = e&31;
      int j0 = n0 + c;
      if (j0 < maxc) g_M4[(orow+m0+r)*NC + ocol + j0] = val;
    }
  }
}

// =============== GF: fused ceff + GEMM-tile (f32x2) + attention + epilogue ===============
#define SG_STRIDE 416   // col offsets: y0=0 (98), y1=98 (129), y2=227 (129), y3=356 (50)
__global__ __launch_bounds__(512) void gf_kernel(
  const float* __restrict__ z,   const float* __restrict__ rw,
  const float* __restrict__ az,  const float* __restrict__ arw,
  const float* __restrict__ acz, const float* __restrict__ ctrl,
  const float* __restrict__ ecov,const float* __restrict__ formb,
  float* __restrict__ out)
{
  __shared__ __align__(16) float xsT[4*64*20];        // [y][i][bb], bb stride 20
  __shared__ float sg[16*SG_STRIDE];                  // [bat][col]
  const int t = threadIdx.x;
  const int b0 = blockIdx.x*16;
  const int w = t>>5, lane = t&31;
  const int b = b0 + w;

  for (int idx=t; idx<3072; idx+=512){
    int y = idx>>10, r = idx&1023, bb = r>>6, i = r&63;
    const float* X = (y==0)? z : (y==1)? az : acz;
    xsT[(y*64+i)*20 + bb] = X[(b0+bb)*ND + i];
  }

  float e0=ecov[b*ND+lane], e1=ecov[b*ND+32+lane];
  float c0g=ctrl[b*ND+lane], c1g=ctrl[b*ND+32+lane];
  float ee = wsum(e0*e0+e1*e1);
  float ec = wsum(e0*c0g+e1*c1g);
  float kk = (ee > 1e-8f) ? ec/fmaxf(ee,1e-8f) : 0.f;
  float ce0 = c0g - kk*e0, ce1 = c1g - kk*e1;
  float fb = wsum(formb[lane]*ce0 + formb[lane+32]*ce1);
  xsT[(3*64+lane)*20 + w]    = ce0;
  xsT[(3*64+32+lane)*20 + w] = ce1;
  __syncthreads();

  if (t < 406){
    int y, col;
    if (t<98){y=0;col=t;} else if (t<227){y=1;col=t-98;}
    else if (t<356){y=2;col=t-227;} else {y=3;col=t-356;}
    const float* M  = g_M4 + (y*ND)*NC + col;
    const float* xb = xsT + (y*64)*20;
    ull acc2[8];
    #pragma unroll
    for (int k=0;k<8;k++) acc2[k] = 0ull;
    #pragma unroll 4
    for (int i=0;i<64;i++){
      ull mv2 = bcast2(M[(size_t)i*NC]);
      const ull* x2 = (const ull*)(xb + i*20);
      #pragma unroll
      for (int k=0;k<8;k++) fma2(acc2[k], mv2, x2[k]);
    }
    float bz = g_bz[y*NC+col];
    #pragma unroll
    for (int k=0;k<8;k++){
      float2 pv = unpack2(acc2[k]);
      sg[(2*k+0)*SG_STRIDE+t] = pv.x + bz;
      sg[(2*k+1)*SG_STRIDE+t] = pv.y + bz;
    }
  }
  __syncthreads();

  const float* gz   = sg + w*SG_STRIDE;
  const float* gaz  = gz + 98;
  const float* gacz = gz + 227;
  const float* gc   = gz + 356;

  float z0  = z[b*ND+lane],   z1  = z[b*ND+32+lane];
  float a0  = az[b*ND+lane],  a1  = az[b*ND+32+lane];
  float c0  = acz[b*ND+lane], c1  = acz[b*ND+32+lane];

  float d_z2   = wsum(z0*z0 + z1*z1);
  float d_zaz  = wsum(z0*a0 + z1*a1);
  float d_az2  = wsum(a0*a0 + a1*a1);
  float d_zacz = wsum(z0*c0 + z1*c1);
  float d_acz2 = wsum(c0*c0 + c1*c1);
  float d_zy1  = wsum(z0*gaz[lane]     + z1*gaz[32+lane]);
  float d_zy2  = wsum(z0*gacz[lane]    + z1*gacz[32+lane]);
  float d_cy3  = wsum(ce0*gaz[64+lane] + ce1*gaz[96+lane]);
  float d_cy4  = wsum(ce0*gacz[64+lane]+ ce1*gacz[96+lane]);

  float s0, t0, s1 = -1e30f, t1 = 0.f;
  {
    int tok = lane;
    if (tok == 0){
      s0 = (d_zy1 + gz[96] + gaz[128])*0.0625f - (d_z2 - 2.f*d_zaz + d_az2);
      t0 = d_cy3 + gc[48];
    } else if (tok == 1){
      s0 = (d_zy2 + gz[97] + gacz[128])*0.0625f - (d_z2 - 2.f*d_zacz + d_acz2);
      t0 = d_cy4 + gc[49];
    } else if (tok < 18){
      int k = tok-2; float aw = arw[b*NKA+k];
      s0 = aw*gz[k]*0.0625f - (d_z2 - 2.f*gz[48+k] + g_aan2[k]);
      t0 = aw*gc[k];
    } else {
      int k = tok-18; float cw = rw[b*NK+k];
      s0 = cw*gz[16+k]*0.0625f - (d_z2 - 2.f*gz[64+k] + g_an2[k]);
      t0 = cw*gc[16+k];
    }
  }
  if (lane < 18){
    int k = lane + 14;     // token lane+32 = chart k = lane+14
    float cw = rw[b*NK+k];
    s1 = cw*gz[16+k]*0.0625f - (d_z2 - 2.f*gz[64+k] + g_an2[k]);
    t1 = cw*gc[16+k];
  }

  float m = wmax(fmaxf(s0, s1));
  float ex0 = __expf(s0 - m);
  float ex1 = (lane < 18) ? __expf(s1 - m) : 0.f;
  float den = wsum(ex0 + ex1);
  float num = wsum(ex0*t0 + ex1*t1);
  if (!lane) out[b] = g_inv_sigma * num / den + fb;
}

// =============== launch ===============
extern "C" void kernel_launch(void* const* d_in, const int* in_sizes, int n_in,
                              void* d_out, int out_size)
{
  const float* z     =(const float*)d_in[0];
  const float* rw    =(const float*)d_in[1];
  const float* az    =(const float*)d_in[2];
  const float* arw   =(const float*)d_in[3];
  const float* acz   =(const float*)d_in[4];
  const float* ctrl  =(const float*)d_in[5];
  const float* ecov  =(const float*)d_in[6];
  const float* cemb  =(const float*)d_in[7];
  const float* canch =(const float*)d_in[8];
  const float* acemb =(const float*)d_in[9];
  const float* acanch=(const float*)d_in[10];
  const float* zW    =(const float*)d_in[11];
  const float* zb    =(const float*)d_in[12];
  const float* latW  =(const float*)d_in[13];
  const float* latb  =(const float*)d_in[14];
  const float* codeW =(const float*)d_in[15];
  const float* codeb =(const float*)d_in[16];
  const float* Wq    =(const float*)d_in[17];
  const float* Wk    =(const float*)d_in[18];
  const float* Wv    =(const float*)d_in[19];
  const float* Wo    =(const float*)d_in[20];
  const float* formW =(const float*)d_in[21];
  const float* formb =(const float*)d_in[22];
  float* out = (float*)d_out;

  p_kernel<<<138,512>>>(zW,latW,codeW,Wq,Wk,Wv,Wo,cemb,acemb,formW,
                        zb,latb,codeb,canch,acanch);
  p2s_kernel<<<28,512>>>(canch,acanch);
  gf_kernel<<<256,512>>>(z,rw,az,arw,acz,ctrl,ecov,formb,out);
}

// round 17
// speedup vs baseline: 1.1488x; 1.0086x over previous
#include <cuda_runtime.h>
#include <cuda_bf16.h>

#define NB  4096
#define ND  64
#define NDM 256
#define NK  32
#define NKA 16
#define NC  160   // M4 row stride; active cols per y: 98,129,129,50

// ----- device scratch -----
__device__ __align__(16) float g_M5[5*ND*NDM];   // Zq, Lk, Lv, Ck, Cv
__device__ __align__(16) float g_B6[5*NDM];      // bq, bLk, bLv, bCk, bCv
__device__ __align__(16) float g_KC[NK*NDM], g_VC[NK*NDM];
__device__ __align__(16) float g_AKC[NKA*NDM], g_AVC[NKA*NDM];
__device__ float g_an2[NK], g_aan2[NKA];
__device__ __align__(16) float g_M2T2[ND*NDM];   // (Wo@form_W)^T : [d][j]
__device__ __align__(16) float g_G[ND*ND];       // form_W^T form_W
__device__ float g_inv_sigma;
__device__ __align__(16) float g_M4[4*ND*NC];    // folded GEMM matrices (pad cols stay 0)
__device__ __align__(16) float g_bz[4*NC];

typedef unsigned long long ull;

__device__ __forceinline__ float wsum(float v){
  #pragma unroll
  for(int o=16;o>0;o>>=1) v += __shfl_xor_sync(0xffffffffu,v,o);
  return v;
}
__device__ __forceinline__ float wmax(float v){
  #pragma unroll
  for(int o=16;o>0;o>>=1) v = fmaxf(v,__shfl_xor_sync(0xffffffffu,v,o));
  return v;
}
__device__ __forceinline__ float dot256(const float* __restrict__ A,
                                        const float* __restrict__ B, int lane){
  float4 a0 = *(const float4*)(A + lane*8);
  float4 a1 = *(const float4*)(A + lane*8 + 4);
  float4 b0 = *(const float4*)(B + lane*8);
  float4 b1 = *(const float4*)(B + lane*8 + 4);
  float s = a0.x*b0.x + a0.y*b0.y + a0.z*b0.z + a0.w*b0.w
          + a1.x*b1.x + a1.y*b1.y + a1.z*b1.z + a1.w*b1.w;
  return wsum(s);
}
// packed fp32x2 helpers
__device__ __forceinline__ ull bcast2(float v){
  ull r;
  asm("mov.b64 %0, {%1, %1};" : "=l"(r) : "r"(__float_as_uint(v)));
  return r;
}
__device__ __forceinline__ void fma2(ull& acc, ull a, ull b){
  asm("fma.rn.f32x2 %0, %1, %2, %0;" : "+l"(acc) : "l"(a), "l"(b));
}
__device__ __forceinline__ float2 unpack2(ull v){
  unsigned int lo, hi;
  asm("mov.b64 {%0, %1}, %2;" : "=r"(lo), "=r"(hi) : "l"(v));
  return make_float2(__uint_as_float(lo), __uint_as_float(hi));
}

// =============== P1: stage-1 folds — split-K 32x32 tiles (verbatim R16) ===============
__global__ __launch_bounds__(512) void p_kernel(
  const float* __restrict__ zW,   const float* __restrict__ latW, const float* __restrict__ codeW,
  const float* __restrict__ Wq,   const float* __restrict__ Wk,   const float* __restrict__ Wv,
  const float* __restrict__ Wo,   const float* __restrict__ cemb, const float* __restrict__ acemb,
  const float* __restrict__ formW,const float* __restrict__ zb,   const float* __restrict__ latb,
  const float* __restrict__ codeb,const float* __restrict__ canch,const float* __restrict__ acanch)
{
  __shared__ float As[2][2080];                 // [h][r*65 + kk]
  __shared__ __align__(16) float Bs[2][2304];   // [h][kk*36 + c]
  int blk = blockIdx.x;
  const int t = threadIdx.x;
  const int w = t>>5, lane = t&31;

  if (blk < 132){
    int g, m0, n0;
    if (blk < 80){ g = blk>>4; int s = blk&15; m0=(s>>3)*32; n0=(s&7)*32; }
    else if (blk < 112){ g = 5 + ((blk-80)>>4); int s=(blk-80)&15; m0=(s>>3)*32; n0=(s&7)*32; }
    else if (blk < 128){ int s=blk-112; g=7; m0=(s>>1)*32; n0=(s&1)*32; }
    else { int s=blk-128; g=8; m0=(s>>1)*32; n0=(s&1)*32; }

    const float* Bm = (g==0)? Wq : (g==1||g==2||g==5)? Wk : (g>=7)? formW : Wv;
    const int ldb = (g>=7)? 64 : 256;

    const int h = w>>3, wi = w&7;
    const int r2 = t>>4, kg = (t&15)*4;       // A load role
    const int kkB = t>>3, c4 = (t&7)*4;       // B load role

    const float* Ap = cemb; bool avalid = true;
    if (g != 8){
      int grow = m0 + r2;
      if (g==0) Ap = zW + grow*256;
      else if (g==1||g==3) Ap = latW + grow*256;
      else if (g==2||g==4) Ap = codeW + grow*256;
      else if (g==7) Ap = Wo + grow*256;
      else {
        if (grow < 32) Ap = cemb + grow*256;
        else if (grow < 48) Ap = acemb + (grow-32)*256;
        else avalid = false;
      }
    }

    float4 apf[2], bpf[2]; float apf_s[2][4];

    auto loadAB = [&](int s){
      #pragma unroll
      for (int hh=0; hh<2; hh++){
        int base = hh*128 + s*64;
        if (g==8){
          #pragma unroll
          for (int p=0;p<4;p++){
            int idx = t + p*512; int kk = idx>>5, r = idx&31;
            apf_s[hh][p] = formW[(base+kk)*64 + m0 + r];
          }
        } else {
          apf[hh] = avalid ? *(const float4*)(Ap + base + kg) : make_float4(0,0,0,0);
        }
        bpf[hh] = *(const float4*)(Bm + (size_t)(base+kkB)*ldb + n0 + c4);
      }
    };
    auto storeAB = [&](){
      #pragma unroll
      for (int hh=0; hh<2; hh++){
        if (g==8){
          #pragma unroll
          for (int p=0;p<4;p++){
            int idx = t + p*512; int kk = idx>>5, r = idx&31;
            As[hh][r*65+kk] = apf_s[hh][p];
          }
        } else {
          float* a = &As[hh][r2*65+kg];
          a[0]=apf[hh].x; a[1]=apf[hh].y; a[2]=apf[hh].z; a[3]=apf[hh].w;
        }
        *(float4*)(&Bs[hh][kkB*36 + c4]) = bpf[hh];
      }
    };

    ull acc2[2] = {0ull, 0ull};
    auto compute = [&](){
      #pragma unroll 8
      for (int kk=0;kk<64;kk++){
        ull av2 = bcast2(As[h][lane*65+kk]);
        const ull* b2 = (const ull*)(&Bs[h][kk*36 + wi*4]);
        fma2(acc2[0], av2, b2[0]);
        fma2(acc2[1], av2, b2[1]);
      }
    };

    loadAB(0); storeAB(); __syncthreads();
    loadAB(1);                         // prefetch step 1
    compute(); __syncthreads();
    storeAB(); __syncthreads();
    compute();

    float2 p01 = unpack2(acc2[0]);
    float2 p23 = unpack2(acc2[1]);
    __syncthreads();
    float* red = &As[0][0];            // 2048 floats [h][c][r]
    red[h*1024 + (wi*4+0)*32 + lane] = p01.x;
    red[h*1024 + (wi*4+1)*32 + lane] = p01.y;
    red[h*1024 + (wi*4+2)*32 + lane] = p23.x;
    red[h*1024 + (wi*4+3)*32 + lane] = p23.y;
    __syncthreads();
    #pragma unroll
    for (int ee=0; ee<2; ee++){
      int e = t + ee*512;
      float val = red[e] + red[1024+e];
      int c = e>>5, r = e&31;
      int grow = m0 + r, gcol = n0 + c;
      if (g<=4){
        const int off[5] = {0,1,3,2,4};   // Zq,Lk,Ck,Lv,Cv slot order
        g_M5[off[g]*(ND*NDM) + grow*NDM + gcol] = val;
      } else if (g<=6){
        if (grow < 48){
          float* C = (grow<32) ? ((g==5)? g_KC : g_VC) + grow*NDM + gcol
                               : ((g==5)? g_AKC : g_AVC) + (grow-32)*NDM + gcol;
          *C = val;
        }
      } else if (g==7){
        g_M2T2[gcol*NDM + grow] = val;
      } else {
        g_G[grow*ND + gcol] = val;
      }
    }
    return;
  }
  blk -= 132;
  if (blk < 5) {                  // folded bias vectors, split-K halves
    const float* vv = (blk==0)? zb : (blk<3 ? latb : codeb);
    const float* Bm = (blk==0)? Wq : ((blk==1||blk==3)? Wk : Wv);
    float* sh = &As[0][0];
    int c = t & 255, hh = t >> 8;
    float s = 0.f;
    #pragma unroll 16
    for (int i=hh*128; i<hh*128+128; i++) s += vv[i]*Bm[i*NDM+c];
    sh[t] = s;
    __syncthreads();
    if (t < 256) g_B6[blk*NDM + t] = sh[t] + sh[256+t];
    return;
  }
  // anchor norms
  if (t < 32) {
    float s=0.f;
    for (int i=0;i<ND;i++){ float v=canch[t*ND+i]; s+=v*v; }
    g_an2[t]=s;
  } else if (t < 48) {
    int k=t-32; float s=0.f;
    for (int i=0;i<ND;i++){ float v=acanch[k*ND+i]; s+=v*v; }
    g_aan2[k]=s;
  }
}

// =============== P2S: sigma | anchors | vectors | 24 split-K GEMM tiles (verbatim R16) ===============
__global__ __launch_bounds__(512) void p2s_kernel(
  const float* __restrict__ canch, const float* __restrict__ acanch)
{
  __shared__ __align__(16) float sm[8768];
  const int blk = blockIdx.x, t = threadIdx.x, w = t>>5, lane = t&31;
  const float* Zq = g_M5;
  const float* Lk = g_M5 + 1*ND*NDM;
  const float* Lv = g_M5 + 2*ND*NDM;
  const float* Ck = g_M5 + 3*ND*NDM;
  const float* Cv = g_M5 + 4*ND*NDM;

  if (blk == 0){
    // ---- sigma: 3 register-tiled squarings (G^8) + 10 power iters + Rayleigh ----
    float* sA = sm; float* sB = sm + 4096; float* sv = sm + 8192;
    #pragma unroll
    for (int r=0;r<8;r++) sA[t + r*512] = g_G[t + r*512];
    __syncthreads();
    const int pr = (t>>4)*2, pc = (t&15)*4;
    for (int sq=0; sq<3; sq++){
      float4 ac0=make_float4(0,0,0,0), ac1=ac0;
      #pragma unroll 4
      for (int q=0;q<64;q++){
        float4 bv = *(const float4*)(sA + q*64 + pc);
        float a0=sA[pr*64+q], a1=sA[(pr+1)*64+q];
        ac0.x+=a0*bv.x; ac0.y+=a0*bv.y; ac0.z+=a0*bv.z; ac0.w+=a0*bv.w;
        ac1.x+=a1*bv.x; ac1.y+=a1*bv.y; ac1.z+=a1*bv.z; ac1.w+=a1*bv.w;
      }
      *(float4*)(sB + (pr+0)*64 + pc) = ac0;
      *(float4*)(sB + (pr+1)*64 + pc) = ac1;
      __syncthreads();
      #pragma unroll
      for (int k=0;k<2;k++) ((float4*)sA)[t*2+k] = ((const float4*)sB)[t*2+k];
      __syncthreads();
    }
    if (t < 32){
      sv[lane]=1.f; sv[lane+32]=1.f; __syncwarp();
      for (int it=0; it<10; it++){
        float y0=0.f, y1=0.f;
        for (int q=0;q<64;q++){ float vq=sv[q]; y0+=sA[q*64+lane]*vq; y1+=sA[q*64+32+lane]*vq; }
        float rn = rsqrtf(wsum(y0*y0+y1*y1));
        sv[lane]=y0*rn; sv[lane+32]=y1*rn; __syncwarp();
      }
      float p0=0.f, p1=0.f;     // Rayleigh on ORIGINAL G
      for (int q=0;q<64;q++){ float vq=sv[q]; p0+=g_G[lane*64+q]*vq; p1+=g_G[(lane+32)*64+q]*vq; }
      float lam = wsum(p0*sv[lane]+p1*sv[lane+32]);
      if (!lane) g_inv_sigma = 1.f/fmaxf(sqrtf(fmaxf(lam,0.f)),1e-8f);
    }
    return;
  }
  if (blk == 1){
    for (int idx=t; idx<3072; idx+=512){
      int i = idx/48, c = idx - i*48;
      g_M4[i*NC + 48 + c] = (c<16)? acanch[c*ND+i] : canch[(c-16)*ND+i];
    }
    return;
  }
  if (blk == 2){
    for (int idx=t; idx<4*NC; idx+=512) g_bz[idx] = 0.f;
    __syncthreads();
    for (int j=w; j<178; j+=16){
      if (j < 48){
        const float* B = (j<16)? g_AKC+j*NDM : g_KC+(j-16)*NDM;
        float s = dot256(g_B6, B, lane);
        if (!lane) g_bz[j] = s;
      } else if (j < 50){
        const float* B = (j==48)? g_B6+NDM : g_B6+3*NDM;
        float s = dot256(g_B6, B, lane);
        if (!lane) g_bz[(j==48)?96:97] = s;
      } else if (j < 114){
        int i = j-50;
        float s = dot256(Zq+i*NDM, g_B6+NDM, lane);
        if (!lane) g_M4[i*NC+96] = s;
      } else {
        int i = j-114;
        float s = dot256(Zq+i*NDM, g_B6+3*NDM, lane);
        if (!lane) g_M4[i*NC+97] = s;
      }
    }
    return;
  }
  if (blk == 3){
    for (int j=w; j<256; j+=16){
      float s; int r, col;
      if (j < 64)      { s = dot256(Lk+j*NDM,          g_B6,       lane); r=64+j;        col=128; }
      else if (j<128)  { s = dot256(Ck+(j-64)*NDM,     g_B6,       lane); r=128+(j-64);  col=128; }
      else if (j<192)  { s = dot256(g_M2T2+(j-128)*NDM,g_B6+2*NDM, lane); r=192+(j-128); col=48;  }
      else             { s = dot256(g_M2T2+(j-192)*NDM,g_B6+4*NDM, lane); r=192+(j-192); col=49;  }
      if (!lane) g_M4[r*NC+col] = s;
    }
    return;
  }
  // ---- tile blocks 4..27 ----
  {
    int tid = blk - 4;            // 0..23
    int typ = tid>>2, sub = tid&3, m0 = (sub>>1)*32, n0 = (sub&1)*32;
    const float* Ab; int orow, ocol, maxc, bsel;
    switch(typ){
      case 0: Ab=Zq;     orow=0;   ocol=0;  maxc=48; bsel=0; break;
      case 1: Ab=Lk;     orow=64;  ocol=0;  maxc=64; bsel=1; break;
      case 2: Ab=Lv;     orow=64;  ocol=64; maxc=64; bsel=2; break;
      case 3: Ab=Ck;     orow=128; ocol=0;  maxc=64; bsel=1; break;
      case 4: Ab=Cv;     orow=128; ocol=64; maxc=64; bsel=2; break;
      default:Ab=g_M2T2; orow=192; ocol=0;  maxc=48; bsel=3; break;
    }
    float* As0 = sm;
    float* Bs0 = sm + 4160;
    const int h = w>>3, wi = w&7;
    const int r2 = t>>4, kg = (t&15)*4;
    const int cB = t>>4, kg2 = (t&15)*4;
    const float* Ap = Ab + (m0+r2)*NDM;
    int cglob = n0 + cB;
    const float* Bp;
    if (bsel==0)      Bp = (cglob<16)? g_AKC + cglob*NDM : (cglob<48)? g_KC + (cglob-16)*NDM : g_AKC;
    else if (bsel==1) Bp = g_M5 + cglob*NDM;
    else if (bsel==2) Bp = g_M2T2 + cglob*NDM;
    else              Bp = (cglob<16)? g_AVC + cglob*NDM : (cglob<48)? g_VC + (cglob-16)*NDM : g_AVC;

    float4 apf[2], bpf[2];
    auto loadAB = [&](int s){
      #pragma unroll
      for (int hh=0; hh<2; hh++){
        int base = hh*128 + s*64;
        apf[hh] = *(const float4*)(Ap + base + kg);
        bpf[hh] = *(const float4*)(Bp + base + kg2);
      }
    };
    auto storeAB = [&](){
      #pragma unroll
      for (int hh=0; hh<2; hh++){
        float* a = As0 + hh*2080 + r2*65 + kg;
        a[0]=apf[hh].x; a[1]=apf[hh].y; a[2]=apf[hh].z; a[3]=apf[hh].w;
        const float* bv = (const float*)&bpf[hh];
        #pragma unroll
        for (int i=0;i<4;i++){
          int kk = kg2+i;
          Bs0[hh*2304 + kk*36 + (cB ^ (kk&28))] = bv[i];
        }
      }
    };

    ull acc2[2] = {0ull, 0ull};
    auto compute = [&](){
      const float* Ah = As0 + h*2080;
      const float* Bh = Bs0 + h*2304;
      #pragma unroll 8
      for (int kk=0;kk<64;kk++){
        ull av2 = bcast2(Ah[lane*65+kk]);
        const ull* b2 = (const ull*)(Bh + kk*36 + ((wi*4) ^ (kk&28)));
        fma2(acc2[0], av2, b2[0]);
        fma2(acc2[1], av2, b2[1]);
      }
    };

    loadAB(0); storeAB(); __syncthreads();
    loadAB(1);
    compute(); __syncthreads();
    storeAB(); __syncthreads();
    compute();

    float2 p01 = unpack2(acc2[0]);
    float2 p23 = unpack2(acc2[1]);
    __syncthreads();
    float* red = sm;               // [h][c][r]
    red[h*1024 + (wi*4+0)*32 + lane] = p01.x;
    red[h*1024 + (wi*4+1)*32 + lane] = p01.y;
    red[h*1024 + (wi*4+2)*32 + lane] = p23.x;
    red[h*1024 + (wi*4+3)*32 + lane] = p23.y;
    __syncthreads();
    #pragma unroll
    for (int ee=0; ee<2; ee++){
      int e = t + ee*512;
      float val = red[e] + red[1024+e];
      int c = e>>5, r = e&31;
      int j0 = n0 + c;
      if (j0 < maxc) g_M4[(orow+m0+r)*NC + ocol + j0] = val;
    }
  }
}

// =============== GF: ceff + broadcast-GEMM + attention + epilogue ===============
#define SG_STRIDE 416   // col offsets: y0=0 (98), y1=98 (129), y2=227 (129), y3=356 (50)
__global__ __launch_bounds__(512) void gf_kernel(
  const float* __restrict__ z,   const float* __restrict__ rw,
  const float* __restrict__ az,  const float* __restrict__ arw,
  const float* __restrict__ acz, const float* __restrict__ ctrl,
  const float* __restrict__ ecov,const float* __restrict__ formb,
  float* __restrict__ out)
{
  __shared__ __align__(16) float xsT[4*64*20];        // [y][i][bb], bb stride 20
  __shared__ float sg[16*SG_STRIDE];                  // [bat][col]
  const int t = threadIdx.x;
  const int b0 = blockIdx.x*16;
  const int w = t>>5, lane = t&31;
  const int b = b0 + w;

  for (int idx=t; idx<3072; idx+=512){
    int y = idx>>10, r = idx&1023, bb = r>>6, i = r&63;
    const float* X = (y==0)? z : (y==1)? az : acz;
    xsT[(y*64+i)*20 + bb] = X[(b0+bb)*ND + i];
  }

  float e0=ecov[b*ND+lane], e1=ecov[b*ND+32+lane];
  float c0g=ctrl[b*ND+lane], c1g=ctrl[b*ND+32+lane];
  float ee = wsum(e0*e0+e1*e1);
  float ec = wsum(e0*c0g+e1*c1g);
  float kk = (ee > 1e-8f) ? ec/fmaxf(ee,1e-8f) : 0.f;
  float ce0 = c0g - kk*e0, ce1 = c1g - kk*e1;
  float fb = wsum(formb[lane]*ce0 + formb[lane+32]*ce1);
  xsT[(3*64+lane)*20 + w]    = ce0;
  xsT[(3*64+32+lane)*20 + w] = ce1;
  __syncthreads();

  // GEMM phase: thread = (batch-half bh, col-pair).
  // Pairs packed per-y: y0 49, y1 65, y2 65, y3 25 = 204 pairs; x2 batch halves = 408 threads.
  if (t < 408){
    int bh = (t >= 204) ? 1 : 0;
    int p  = t - bh*204;
    int y, c0;
    if      (p < 49) { y=0; c0 = 2*p; }
    else if (p <114) { y=1; c0 = 2*(p-49); }
    else if (p <179) { y=2; c0 = 2*(p-114); }
    else             { y=3; c0 = 2*(p-179); }
    const int colsY = (y==0)? 98 : (y==3)? 50 : 129;
    const bool c1v = (c0+1) < colsY;           // pad col (y1/y2 c0=128) reads zeros, store skipped
    const int ybase = (y==0)? 0 : (y==1)? 98 : (y==2)? 227 : 356;

    const float* M  = g_M4 + (y*ND)*NC + c0;
    const float* xb = xsT + (y*64)*20 + bh*8;
    ull acc0[4], acc1[4];
    #pragma unroll
    for (int j=0;j<4;j++){ acc0[j]=0ull; acc1[j]=0ull; }
    #pragma unroll 4
    for (int i=0;i<64;i++){
      const ull* x2 = (const ull*)(xb + i*20);   // 8 batches: 2x LDS.128 broadcast
      ull xv0 = x2[0], xv1 = x2[1], xv2 = x2[2], xv3 = x2[3];
      float2 mv = *(const float2*)(M + (size_t)i*NC);
      ull m0 = bcast2(mv.x), m1 = bcast2(mv.y);
      fma2(acc0[0], m0, xv0); fma2(acc0[1], m0, xv1);
      fma2(acc0[2], m0, xv2); fma2(acc0[3], m0, xv3);
      fma2(acc1[0], m1, xv0); fma2(acc1[1], m1, xv1);
      fma2(acc1[2], m1, xv2); fma2(acc1[3], m1, xv3);
    }
    float bz0 = g_bz[y*NC+c0];
    float bz1 = g_bz[y*NC+c0+1];
    int gcol = ybase + c0;
    #pragma unroll
    for (int j=0;j<4;j++){
      float2 v0 = unpack2(acc0[j]);
      int bat = bh*8 + 2*j;
      sg[(bat+0)*SG_STRIDE + gcol] = v0.x + bz0;
      sg[(bat+1)*SG_STRIDE + gcol] = v0.y + bz0;
      if (c1v){
        float2 v1 = unpack2(acc1[j]);
        sg[(bat+0)*SG_STRIDE + gcol+1] = v1.x + bz1;
        sg[(bat+1)*SG_STRIDE + gcol+1] = v1.y + bz1;
      }
    }
  }
  __syncthreads();

  const float* gz   = sg + w*SG_STRIDE;
  const float* gaz  = gz + 98;
  const float* gacz = gz + 227;
  const float* gc   = gz + 356;

  float z0  = z[b*ND+lane],   z1  = z[b*ND+32+lane];
  float a0  = az[b*ND+lane],  a1  = az[b*ND+32+lane];
  float c0  = acz[b*ND+lane], c1  = acz[b*ND+32+lane];

  float d_z2   = wsum(z0*z0 + z1*z1);
  float d_zaz  = wsum(z0*a0 + z1*a1);
  float d_az2  = wsum(a0*a0 + a1*a1);
  float d_zacz = wsum(z0*c0 + z1*c1);
  float d_acz2 = wsum(c0*c0 + c1*c1);
  float d_zy1  = wsum(z0*gaz[lane]     + z1*gaz[32+lane]);
  float d_zy2  = wsum(z0*gacz[lane]    + z1*gacz[32+lane]);
  float d_cy3  = wsum(ce0*gaz[64+lane] + ce1*gaz[96+lane]);
  float d_cy4  = wsum(ce0*gacz[64+lane]+ ce1*gacz[96+lane]);

  float s0, t0, s1 = -1e30f, t1 = 0.f;
  {
    int tok = lane;
    if (tok == 0){
      s0 = (d_zy1 + gz[96] + gaz[128])*0.0625f - (d_z2 - 2.f*d_zaz + d_az2);
      t0 = d_cy3 + gc[48];
    } else if (tok == 1){
      s0 = (d_zy2 + gz[97] + gacz[128])*0.0625f - (d_z2 - 2.f*d_zacz + d_acz2);
      t0 = d_cy4 + gc[49];
    } else if (tok < 18){
      int k = tok-2; float aw = arw[b*NKA+k];
      s0 = aw*gz[k]*0.0625f - (d_z2 - 2.f*gz[48+k] + g_aan2[k]);
      t0 = aw*gc[k];
    } else {
      int k = tok-18; float cw = rw[b*NK+k];
      s0 = cw*gz[16+k]*0.0625f - (d_z2 - 2.f*gz[64+k] + g_an2[k]);
      t0 = cw*gc[16+k];
    }
  }
  if (lane < 18){
    int k = lane + 14;     // token lane+32 = chart k = lane+14
    float cw = rw[b*NK+k];
    s1 = cw*gz[16+k]*0.0625f - (d_z2 - 2.f*gz[64+k] + g_an2[k]);
    t1 = cw*gc[16+k];
  }

  float m = wmax(fmaxf(s0, s1));
  float ex0 = __expf(s0 - m);
  float ex1 = (lane < 18) ? __expf(s1 - m) : 0.f;
  float den = wsum(ex0 + ex1);
  float num = wsum(ex0*t0 + ex1*t1);
  if (!lane) out[b] = g_inv_sigma * num / den + fb;
}

// =============== launch ===============
extern "C" void kernel_launch(void* const* d_in, const int* in_sizes, int n_in,
                              void* d_out, int out_size)
{
  const float* z     =(const float*)d_in[0];
  const float* rw    =(const float*)d_in[1];
  const float* az    =(const float*)d_in[2];
  const float* arw   =(const float*)d_in[3];
  const float* acz   =(const float*)d_in[4];
  const float* ctrl  =(const float*)d_in[5];
  const float* ecov  =(const float*)d_in[6];
  const float* cemb  =(const float*)d_in[7];
  const float* canch =(const float*)d_in[8];
  const float* acemb =(const float*)d_in[9];
  const float* acanch=(const float*)d_in[10];
  const float* zW    =(const float*)d_in[11];
  const float* zb    =(const float*)d_in[12];
  const float* latW  =(const float*)d_in[13];
  const float* latb  =(const float*)d_in[14];
  const float* codeW =(const float*)d_in[15];
  const float* codeb =(const float*)d_in[16];
  const float* Wq    =(const float*)d_in[17];
  const float* Wk    =(const float*)d_in[18];
  const float* Wv    =(const float*)d_in[19];
  const float* Wo    =(const float*)d_in[20];
  const float* formW =(const float*)d_in[21];
  const float* formb =(const float*)d_in[22];
  float* out = (float*)d_out;

  p_kernel<<<138,512>>>(zW,latW,codeW,Wq,Wk,Wv,Wo,cemb,acemb,formW,
                        zb,latb,codeb,canch,acanch);
  p2s_kernel<<<28,512>>>(canch,acanch);
  gf_kernel<<<256,512>>>(z,rw,az,arw,acz,ctrl,ecov,formb,out);
}